// round 8
// baseline (speedup 1.0000x reference)
#include <cuda_runtime.h>
#include <cuda_bf16.h>
#include <math.h>
#include <stdint.h>

// Problem constants
#define BB   16
#define CC   32
#define TT   62
#define VV   19
#define DD   128
#define HH   8
#define HDm  256
#define NBT  (BB*TT)      // 992
#define NTOK (NBT*VV)     // 18848
#define NPAIR (VV*VV)     // 361

// ---------------- scratch buffers ----------------
__device__ float d_p   [NTOK*CC];
__device__ float d_y   [NTOK*DD];
__device__ float d_e   [NTOK*HDm];
__device__ float d_bias[NBT*NPAIR*HH];
__device__ float d_qkv [NTOK*384];
__device__ float d_a   [NTOK*DD];
__device__ float d_y1  [NTOK*DD];
__device__ float d_h   [NTOK*HDm];
__device__ float d_f   [NTOK*DD];
__device__ float d_mem [NTOK*DD];
__device__ float d_pe  [TT*DD];

// ---------------- p builder ----------------
__global__ void build_p_kernel(const float* __restrict__ pose) {
    int idx = blockIdx.x * 256 + threadIdx.x;
    if (idx >= NTOK * CC) return;
    int c  = idx & 31;
    int v  = (idx >> 5) % VV;
    int bt = idx / (CC * VV);
    int b = bt / TT, t = bt % TT;
    d_p[idx] = pose[(((size_t)b * CC + c) * TT + t) * VV + v];
}

// ---------------- positional encoding ----------------
__global__ void build_pe_kernel() {
    int t = blockIdx.x, c = threadIdx.x;
    int i2 = c & ~1;
    float div = expf((float)i2 * (-9.210340371976184f / 128.f));
    float ang = (float)t * div;
    d_pe[t * DD + c] = (c & 1) ? cosf(ang) : sinf(ang);
}

// ================= bf16-split tensor-core GEMM =================
// C = act(A[M,K] @ W[N,K]^T + bias), split: A=Ah+Al, B=Bh+Bl (bf16 each)
// C ≈ Ah*Bh + Ah*Bl + Al*Bh  (fp32 accum)
// act 0: none; 1: relu; 2: leakyrelu(0.01); 3: += pe[row%62][col], write C,C2 (N==128)
#define BMt 128
#define BNt 128
#define BKt 32
#define KP  18   // u32 columns per row (16 data + 2 pad) -> conflict-free frag LDS

__device__ __forceinline__ void cvt_split2(float x, float y, uint32_t& hi, uint32_t& lo) {
    __nv_bfloat16 xh = __float2bfloat16(x);
    __nv_bfloat16 yh = __float2bfloat16(y);
    __nv_bfloat16 xl = __float2bfloat16(x - __bfloat162float(xh));
    __nv_bfloat16 yl = __float2bfloat16(y - __bfloat162float(yh));
    hi = ((uint32_t)__bfloat16_as_ushort(yh) << 16) | (uint32_t)__bfloat16_as_ushort(xh);
    lo = ((uint32_t)__bfloat16_as_ushort(yl) << 16) | (uint32_t)__bfloat16_as_ushort(xl);
}

__device__ __forceinline__ void mma16816(float (&c)[4], const uint32_t (&a)[4],
                                         uint32_t b0, uint32_t b1) {
    asm volatile(
        "mma.sync.aligned.m16n8k16.row.col.f32.bf16.bf16.f32 "
        "{%0,%1,%2,%3}, {%4,%5,%6,%7}, {%8,%9}, {%0,%1,%2,%3};"
        : "+f"(c[0]), "+f"(c[1]), "+f"(c[2]), "+f"(c[3])
        : "r"(a[0]), "r"(a[1]), "r"(a[2]), "r"(a[3]), "r"(b0), "r"(b1));
}

__global__ __launch_bounds__(256, 2)
void gemm_tc_kernel(const float* __restrict__ A, const float* __restrict__ W,
                    const float* __restrict__ bias, float* __restrict__ C,
                    float* __restrict__ C2, int M, int N, int K, int act)
{
    __shared__ uint32_t Ah_s[BMt][KP], Al_s[BMt][KP];
    __shared__ uint32_t Bh_s[BNt][KP], Bl_s[BNt][KP];

    int tid = threadIdx.x, lane = tid & 31, wid = tid >> 5;
    int m0 = blockIdx.x * BMt, n0 = blockIdx.y * BNt;
    int wm = (wid & 1) * 64, wn = (wid >> 1) * 32;    // warp tile 64x32
    int gr = lane >> 2, gc = lane & 3;

    // loader mapping: 2 threads per row, each loads 16 contiguous k (4 float4)
    int lrow = tid >> 1, lkh = (tid & 1) * 16;

    float acc[4][4][4];
    #pragma unroll
    for (int mt = 0; mt < 4; mt++)
        #pragma unroll
        for (int nt = 0; nt < 4; nt++)
            #pragma unroll
            for (int e = 0; e < 4; e++) acc[mt][nt][e] = 0.f;

    for (int k0 = 0; k0 < K; k0 += BKt) {
        __syncthreads();
        {   // A tile: rows m0+lrow, k [k0+lkh, +16)
            bool ok = (m0 + lrow) < M;
            const float* src = A + (size_t)(m0 + lrow) * K + k0 + lkh;
            #pragma unroll
            for (int q = 0; q < 4; q++) {
                float4 v = ok ? *(const float4*)(src + q * 4) : make_float4(0.f,0.f,0.f,0.f);
                uint32_t h0, l0, h1, l1;
                cvt_split2(v.x, v.y, h0, l0);
                cvt_split2(v.z, v.w, h1, l1);
                int cb = (lkh >> 1) + q * 2;
                Ah_s[lrow][cb] = h0;   Ah_s[lrow][cb + 1] = h1;
                Al_s[lrow][cb] = l0;   Al_s[lrow][cb + 1] = l1;
            }
        }
        {   // B tile: rows n0+lrow of W
            bool ok = (n0 + lrow) < N;
            const float* src = W + (size_t)(n0 + lrow) * K + k0 + lkh;
            #pragma unroll
            for (int q = 0; q < 4; q++) {
                float4 v = ok ? *(const float4*)(src + q * 4) : make_float4(0.f,0.f,0.f,0.f);
                uint32_t h0, l0, h1, l1;
                cvt_split2(v.x, v.y, h0, l0);
                cvt_split2(v.z, v.w, h1, l1);
                int cb = (lkh >> 1) + q * 2;
                Bh_s[lrow][cb] = h0;   Bh_s[lrow][cb + 1] = h1;
                Bl_s[lrow][cb] = l0;   Bl_s[lrow][cb + 1] = l1;
            }
        }
        __syncthreads();

        #pragma unroll
        for (int ks = 0; ks < 2; ks++) {           // two k16 steps per BK32
            int cb = ks * 8;
            uint32_t aH[4][4], aL[4][4];
            #pragma unroll
            for (int mt = 0; mt < 4; mt++) {
                int r = wm + mt * 16;
                aH[mt][0] = Ah_s[r + gr    ][cb + gc];
                aH[mt][1] = Ah_s[r + gr + 8][cb + gc];
                aH[mt][2] = Ah_s[r + gr    ][cb + gc + 4];
                aH[mt][3] = Ah_s[r + gr + 8][cb + gc + 4];
                aL[mt][0] = Al_s[r + gr    ][cb + gc];
                aL[mt][1] = Al_s[r + gr + 8][cb + gc];
                aL[mt][2] = Al_s[r + gr    ][cb + gc + 4];
                aL[mt][3] = Al_s[r + gr + 8][cb + gc + 4];
            }
            #pragma unroll
            for (int nt = 0; nt < 4; nt++) {
                int c = wn + nt * 8 + gr;
                uint32_t bH0 = Bh_s[c][cb + gc], bH1 = Bh_s[c][cb + gc + 4];
                uint32_t bL0 = Bl_s[c][cb + gc], bL1 = Bl_s[c][cb + gc + 4];
                #pragma unroll
                for (int mt = 0; mt < 4; mt++) {
                    mma16816(acc[mt][nt], aH[mt], bH0, bH1);
                    mma16816(acc[mt][nt], aH[mt], bL0, bL1);
                    mma16816(acc[mt][nt], aL[mt], bH0, bH1);
                }
            }
        }
    }

    // ---- epilogue ----
    #pragma unroll
    for (int mt = 0; mt < 4; mt++) {
        #pragma unroll
        for (int rr = 0; rr < 2; rr++) {
            int row = m0 + wm + mt * 16 + gr + rr * 8;
            if (row >= M) continue;
            #pragma unroll
            for (int nt = 0; nt < 4; nt++) {
                int col = n0 + wn + nt * 8 + gc * 2;
                if (col >= N) continue;
                float v0 = acc[mt][nt][rr * 2];
                float v1 = acc[mt][nt][rr * 2 + 1];
                if (bias) { v0 += bias[col]; v1 += bias[col + 1]; }
                if (act == 1) { v0 = fmaxf(v0, 0.f); v1 = fmaxf(v1, 0.f); }
                else if (act == 2) {
                    v0 = (v0 >= 0.f) ? v0 : 0.01f * v0;
                    v1 = (v1 >= 0.f) ? v1 : 0.01f * v1;
                }
                else if (act == 3) {
                    v0 += d_pe[(row % TT) * DD + (col & 127)];
                    v1 += d_pe[(row % TT) * DD + ((col + 1) & 127)];
                }
                float* cp = C + (size_t)row * N + col;
                cp[0] = v0; cp[1] = v1;
                if (act == 3) {
                    float* c2 = C2 + (size_t)row * N + col;
                    c2[0] = v0; c2[1] = v1;
                }
            }
        }
    }
}

// ---------------- fused pairwise bias ----------------
__global__ __launch_bounds__(256)
void bias_kernel(const float* __restrict__ E, const float* __restrict__ WB,
                 const float* __restrict__ prelu_a, int iter, float* __restrict__ OUT)
{
    __shared__ float es[VV * HDm];
    __shared__ float wb[HH * HDm];
    int bt = blockIdx.x;
    int tid = threadIdx.x;
    for (int idx = tid; idx < VV * HDm; idx += 256)
        es[idx] = E[((size_t)bt * VV) * HDm + idx];
    for (int idx = tid; idx < HH * HDm; idx += 256)
        wb[idx] = WB[idx];
    float aP = prelu_a[iter];
    __syncthreads();

    int warp = tid >> 5, lane = tid & 31;
    for (int pr = warp; pr < NPAIR; pr += 8) {
        int vi = pr / VV, vj = pr % VV;
        float acc[8] = {0,0,0,0,0,0,0,0};
        #pragma unroll
        for (int u = 0; u < 8; u++) {
            int k = u * 32 + lane;
            float hv = es[vj * HDm + k] - es[vi * HDm + k];
            hv = (hv >= 0.f) ? hv : aP * hv;
            #pragma unroll
            for (int g = 0; g < 8; g++) acc[g] += hv * wb[g * HDm + k];
        }
        #pragma unroll
        for (int g = 0; g < 8; g++)
            #pragma unroll
            for (int o = 16; o; o >>= 1)
                acc[g] += __shfl_xor_sync(0xffffffffu, acc[g], o);
        if (lane == 0) {
            float* o = OUT + (((size_t)bt * VV + vi) * VV + vj) * HH;
            #pragma unroll
            for (int g = 0; g < 8; g++) o[g] = acc[g] * 0.3535533906f;
        }
    }
}

// ---------------- graph attention (N=19, per-head bias) ----------------
__global__ __launch_bounds__(256)
void graph_attn_kernel(const float* __restrict__ QKV, const float* __restrict__ BIAS,
                       float* __restrict__ OUT)
{
    __shared__ float qs[VV * DD];
    __shared__ float ks[DD * VV];
    __shared__ float vs[DD * VV];
    int bt = blockIdx.x;
    int tid = threadIdx.x;
    for (int idx = tid; idx < VV * DD; idx += 256) {
        int n = idx >> 7, c = idx & 127;
        const float* row = QKV + (size_t)(bt * VV + n) * 384;
        qs[idx] = row[c];
        ks[c * VV + n] = row[128 + c];
        vs[c * VV + n] = row[256 + c];
    }
    __syncthreads();
    int h = tid >> 5, lane = tid & 31;
    for (int i = 0; i < VV; i++) {
        float sc = -1e30f;
        if (lane < VV) {
            float acc = 0.f;
            #pragma unroll
            for (int c = 0; c < 16; c++)
                acc += qs[i * DD + h * 16 + c] * ks[(h * 16 + c) * VV + lane];
            sc = acc * 0.25f + BIAS[(((size_t)bt * VV + i) * VV + lane) * HH + h];
        }
        float mx = sc;
        #pragma unroll
        for (int o = 16; o; o >>= 1) mx = fmaxf(mx, __shfl_xor_sync(0xffffffffu, mx, o));
        float ev = (lane < VV) ? __expf(sc - mx) : 0.f;
        float sum = ev;
        #pragma unroll
        for (int o = 16; o; o >>= 1) sum += __shfl_xor_sync(0xffffffffu, sum, o);
        float aj = ev / sum;
        float o_acc = 0.f;
        int cc = lane & 15;
        #pragma unroll
        for (int j = 0; j < VV; j++) {
            float aw = __shfl_sync(0xffffffffu, aj, j);
            o_acc += aw * vs[(h * 16 + cc) * VV + j];
        }
        if (lane < 16) OUT[(size_t)(bt * VV + i) * DD + h * 16 + lane] = o_acc;
    }
}

// ---------------- temporal attention (N=62, no bias) ----------------
__global__ __launch_bounds__(128)
void temporal_attn_kernel(const float* __restrict__ QKV, float* __restrict__ OUT)
{
    __shared__ float ks[16 * 65];
    __shared__ float vs[16 * 65];
    int bn = blockIdx.x, h = blockIdx.y;
    int tid = threadIdx.x;
    for (int idx = tid; idx < 16 * 64; idx += 128) {
        int c = idx >> 6, n = idx & 63;
        float kv = 0.f, vv = 0.f;
        if (n < TT) {
            const float* row = QKV + (size_t)(bn * TT + n) * 384 + h * 16 + c;
            kv = row[128];
            vv = row[256];
        }
        ks[c * 65 + n] = kv;
        vs[c * 65 + n] = vv;
    }
    __syncthreads();
    int warp = tid >> 5, lane = tid & 31;
    for (int i = warp; i < TT; i += 4) {
        float q = (lane < 16) ? QKV[(size_t)(bn * TT + i) * 384 + h * 16 + lane] : 0.f;
        float s0 = 0.f, s1 = 0.f;
        #pragma unroll
        for (int c = 0; c < 16; c++) {
            float qc = __shfl_sync(0xffffffffu, q, c);
            s0 += qc * ks[c * 65 + lane];
            s1 += qc * ks[c * 65 + lane + 32];
        }
        s0 *= 0.25f; s1 *= 0.25f;
        bool v1 = (lane + 32) < TT;
        float mx = fmaxf(s0, v1 ? s1 : -1e30f);
        #pragma unroll
        for (int o = 16; o; o >>= 1) mx = fmaxf(mx, __shfl_xor_sync(0xffffffffu, mx, o));
        float e0 = __expf(s0 - mx);
        float e1 = v1 ? __expf(s1 - mx) : 0.f;
        float sum = e0 + e1;
        #pragma unroll
        for (int o = 16; o; o >>= 1) sum += __shfl_xor_sync(0xffffffffu, sum, o);
        float inv = 1.f / sum;
        e0 *= inv; e1 *= inv;
        float o_acc = 0.f;
        int cc = lane & 15;
        #pragma unroll
        for (int j = 0; j < 32; j++) {
            float aw = __shfl_sync(0xffffffffu, e0, j);
            o_acc += aw * vs[cc * 65 + j];
        }
        #pragma unroll
        for (int j = 32; j < TT; j++) {
            float aw = __shfl_sync(0xffffffffu, e1, j - 32);
            o_acc += aw * vs[cc * 65 + j];
        }
        if (lane < 16) OUT[(size_t)(bn * TT + i) * DD + h * 16 + lane] = o_acc;
    }
}

// ---------------- LayerNorm: out = LN(X + R) * g + b (+ ADD) ----------------
__global__ __launch_bounds__(256)
void ln_kernel(const float* __restrict__ X, const float* __restrict__ R,
               const float* __restrict__ g, const float* __restrict__ b,
               float* __restrict__ OUT, const float* __restrict__ ADD)
{
    int warp = threadIdx.x >> 5, lane = threadIdx.x & 31;
    int row = blockIdx.x * 8 + warp;
    if (row >= NTOK) return;
    const float* x = X + (size_t)row * DD;
    const float* r = R + (size_t)row * DD;
    float v[4];
    #pragma unroll
    for (int u = 0; u < 4; u++) v[u] = x[lane + u * 32] + r[lane + u * 32];
    float s = v[0] + v[1] + v[2] + v[3];
    #pragma unroll
    for (int o = 16; o; o >>= 1) s += __shfl_xor_sync(0xffffffffu, s, o);
    float m = s * (1.f / 128.f);
    float sv = 0.f;
    #pragma unroll
    for (int u = 0; u < 4; u++) { float dlt = v[u] - m; sv += dlt * dlt; }
    #pragma unroll
    for (int o = 16; o; o >>= 1) sv += __shfl_xor_sync(0xffffffffu, sv, o);
    float rinv = rsqrtf(sv * (1.f / 128.f) + 1e-5f);
    #pragma unroll
    for (int u = 0; u < 4; u++) {
        int c = lane + u * 32;
        float o = (v[u] - m) * rinv * g[c] + b[c];
        if (ADD) o += ADD[(size_t)row * DD + c];
        OUT[(size_t)row * DD + c] = o;
    }
}

// ---------------- host launcher ----------------
static void GEMM(const float* A, const float* W, const float* bias, float* C,
                 int M, int N, int K, int act, float* C2 = nullptr)
{
    dim3 grid((M + BMt - 1) / BMt, (N + BNt - 1) / BNt);
    gemm_tc_kernel<<<grid, 256>>>(A, W, bias, C, C2, M, N, K, act);
}

extern "C" void kernel_launch(void* const* d_in, const int* in_sizes, int n_in,
                              void* d_out, int out_size)
{
    const float* pose    = (const float*)d_in[0];
    const float* W_pose  = (const float*)d_in[1];
    const float* W_emb   = (const float*)d_in[2];
    const float* prelu_a = (const float*)d_in[3];
    const float* W_bias  = (const float*)d_in[4];
    const float* gWqkv   = (const float*)d_in[5];
    const float* gbqkv   = (const float*)d_in[6];
    const float* gWo     = (const float*)d_in[7];
    const float* gbo     = (const float*)d_in[8];
    const float* gln1g   = (const float*)d_in[9];
    const float* gln1b   = (const float*)d_in[10];
    const float* gW1     = (const float*)d_in[11];
    const float* gb1     = (const float*)d_in[12];
    const float* gW2     = (const float*)d_in[13];
    const float* gb2     = (const float*)d_in[14];
    const float* gln2g   = (const float*)d_in[15];
    const float* gln2b   = (const float*)d_in[16];
    const float* deW     = (const float*)d_in[17];
    const float* deb     = (const float*)d_in[18];
    const float* tWqkv   = (const float*)d_in[19];
    const float* tbqkv   = (const float*)d_in[20];
    const float* tWo     = (const float*)d_in[21];
    const float* tbo     = (const float*)d_in[22];
    const float* tln1g   = (const float*)d_in[23];
    const float* tln1b   = (const float*)d_in[24];
    const float* tW1     = (const float*)d_in[25];
    const float* tb1     = (const float*)d_in[26];
    const float* tW2     = (const float*)d_in[27];
    const float* tb2     = (const float*)d_in[28];
    const float* tln2g   = (const float*)d_in[29];
    const float* tln2b   = (const float*)d_in[30];
    const float* W_out   = (const float*)d_in[31];
    float* out = (float*)d_out;

    float *p_, *y_, *e_, *bias_, *qkv_, *a_, *y1_, *h_, *f_, *mem_;
    cudaGetSymbolAddress((void**)&p_,    d_p);
    cudaGetSymbolAddress((void**)&y_,    d_y);
    cudaGetSymbolAddress((void**)&e_,    d_e);
    cudaGetSymbolAddress((void**)&bias_, d_bias);
    cudaGetSymbolAddress((void**)&qkv_,  d_qkv);
    cudaGetSymbolAddress((void**)&a_,    d_a);
    cudaGetSymbolAddress((void**)&y1_,   d_y1);
    cudaGetSymbolAddress((void**)&h_,    d_h);
    cudaGetSymbolAddress((void**)&f_,    d_f);
    cudaGetSymbolAddress((void**)&mem_,  d_mem);

    build_p_kernel<<<(NTOK * CC + 255) / 256, 256>>>(pose);
    build_pe_kernel<<<TT, DD>>>();
    GEMM(p_, W_pose, nullptr, y_, NTOK, DD, CC, 0);

    for (int it = 0; it < 2; it++) {
        // ---- pairwise bias (linear-in-diff trick) ----
        GEMM(p_, W_emb + (size_t)it * HDm * CC, nullptr, e_, NTOK, HDm, CC, 0);
        bias_kernel<<<NBT, 256>>>(e_, W_bias + (size_t)it * HH * HDm, prelu_a, it, bias_);

        // ---- graph encoder block (rows = bt*19+v) ----
        GEMM(y_, gWqkv + (size_t)it * 3 * DD * DD, gbqkv + (size_t)it * 3 * DD,
             qkv_, NTOK, 384, DD, 0);
        graph_attn_kernel<<<NBT, 256>>>(qkv_, bias_, a_);
        GEMM(a_, gWo + (size_t)it * DD * DD, gbo + (size_t)it * DD, f_, NTOK, DD, DD, 0);
        ln_kernel<<<(NTOK + 7) / 8, 256>>>(f_, y_, gln1g + it * DD, gln1b + it * DD, y1_, nullptr);
        GEMM(y1_, gW1 + (size_t)it * HDm * DD, gb1 + (size_t)it * HDm, h_, NTOK, HDm, DD, 1);
        GEMM(h_, gW2 + (size_t)it * DD * HDm, gb2 + (size_t)it * DD, f_, NTOK, DD, HDm, 0);
        ln_kernel<<<(NTOK + 7) / 8, 256>>>(f_, y1_, gln2g + it * DD, gln2b + it * DD, a_, nullptr);
        // de linear + pe -> y and mem
        GEMM(a_, deW + (size_t)it * DD * DD, deb + (size_t)it * DD, y_, NTOK, DD, DD, 3, mem_);

        // ---- temporal encoder block (rows = m*62+t) ----
        GEMM(y_, tWqkv + (size_t)it * 3 * DD * DD, tbqkv + (size_t)it * 3 * DD,
             qkv_, NTOK, 384, DD, 0);
        {
            dim3 grid(BB * VV, HH);
            temporal_attn_kernel<<<grid, 128>>>(qkv_, a_);
        }
        GEMM(a_, tWo + (size_t)it * DD * DD, tbo + (size_t)it * DD, f_, NTOK, DD, DD, 0);
        ln_kernel<<<(NTOK + 7) / 8, 256>>>(f_, y_, tln1g + it * DD, tln1b + it * DD, y1_, nullptr);
        GEMM(y1_, tW1 + (size_t)it * HDm * DD, tb1 + (size_t)it * HDm, h_, NTOK, HDm, DD, 1);
        GEMM(h_, tW2 + (size_t)it * DD * HDm, tb2 + (size_t)it * DD, f_, NTOK, DD, HDm, 0);
        ln_kernel<<<(NTOK + 7) / 8, 256>>>(f_, y1_, tln2g + it * DD, tln2b + it * DD, y_, mem_);
    }

    // out = leakyrelu(y @ W_out^T)
    GEMM(y_, W_out, nullptr, out, NTOK, 64, DD, 2);
}

// round 9
// speedup vs baseline: 1.6455x; 1.6455x over previous
#include <cuda_runtime.h>
#include <cuda_bf16.h>
#include <math.h>
#include <stdint.h>

// Problem constants
#define BB   16
#define CC   32
#define TT   62
#define VV   19
#define DD   128
#define HH   8
#define HDm  256
#define NBT  (BB*TT)      // 992
#define NTOK (NBT*VV)     // 18848
#define NPAIR (VV*VV)     // 361

// ---------------- scratch buffers ----------------
__device__ float d_p   [NTOK*CC];
__device__ float d_y   [NTOK*DD];
__device__ float d_e   [NTOK*HDm];
__device__ float d_bias[NBT*NPAIR*HH];
__device__ float d_qkv [NTOK*384];
__device__ float d_a   [NTOK*DD];
__device__ float d_y1  [NTOK*DD];
__device__ float d_h   [NTOK*HDm];
__device__ float d_f   [NTOK*DD];
__device__ float d_mem [NTOK*DD];
__device__ float d_pe  [TT*DD];
// pre-split weights (bf16 hi/lo packed as u32 = 2 bf16)
#define WTOT 292864
__device__ uint32_t d_wh[WTOT];
__device__ uint32_t d_wl[WTOT];

// ---------------- helpers ----------------
__device__ __forceinline__ void cvt_split2(float x, float y, uint32_t& hi, uint32_t& lo) {
    __nv_bfloat16 xh = __float2bfloat16(x);
    __nv_bfloat16 yh = __float2bfloat16(y);
    __nv_bfloat16 xl = __float2bfloat16(x - __bfloat162float(xh));
    __nv_bfloat16 yl = __float2bfloat16(y - __bfloat162float(yh));
    hi = ((uint32_t)__bfloat16_as_ushort(yh) << 16) | (uint32_t)__bfloat16_as_ushort(xh);
    lo = ((uint32_t)__bfloat16_as_ushort(yl) << 16) | (uint32_t)__bfloat16_as_ushort(xl);
}

__device__ __forceinline__ void mma16816(float (&c)[4], const uint32_t (&a)[4],
                                         uint32_t b0, uint32_t b1) {
    asm volatile(
        "mma.sync.aligned.m16n8k16.row.col.f32.bf16.bf16.f32 "
        "{%0,%1,%2,%3}, {%4,%5,%6,%7}, {%8,%9}, {%0,%1,%2,%3};"
        : "+f"(c[0]), "+f"(c[1]), "+f"(c[2]), "+f"(c[3])
        : "r"(a[0]), "r"(a[1]), "r"(a[2]), "r"(a[3]), "r"(b0), "r"(b1));
}

__device__ __forceinline__ void ldsm4(uint32_t (&r)[4], uint32_t base, int row, int ks, int chalf) {
    int chunk = 2 * ks + chalf;
    int cp = chunk ^ ((row & 6) >> 1);
    uint32_t addr = base + (uint32_t)(row * 64 + cp * 16);
    asm volatile("ldmatrix.sync.aligned.m8n8.x4.shared.b16 {%0,%1,%2,%3}, [%4];"
        : "=r"(r[0]), "=r"(r[1]), "=r"(r[2]), "=r"(r[3]) : "r"(addr));
}

// ---------------- p builder ----------------
__global__ void build_p_kernel(const float* __restrict__ pose) {
    int idx = blockIdx.x * 256 + threadIdx.x;
    if (idx >= NTOK * CC) return;
    int c  = idx & 31;
    int v  = (idx >> 5) % VV;
    int bt = idx / (CC * VV);
    int b = bt / TT, t = bt % TT;
    d_p[idx] = pose[(((size_t)b * CC + c) * TT + t) * VV + v];
}

// ---------------- positional encoding ----------------
__global__ void build_pe_kernel() {
    int t = blockIdx.x, c = threadIdx.x;
    int i2 = c & ~1;
    float div = expf((float)i2 * (-9.210340371976184f / 128.f));
    float ang = (float)t * div;
    d_pe[t * DD + c] = (c & 1) ? cosf(ang) : sinf(ang);
}

// ---------------- weight pre-split ----------------
#define NW 22
struct PrepList {
    const float* src[NW];
    int off[NW];
    int n[NW];
};
__global__ void split_weights_kernel(PrepList pl) {
    int wi = blockIdx.y;
    const float* s = pl.src[wi];
    int off = pl.off[wi], n = pl.n[wi];
    for (int i = blockIdx.x * blockDim.x + threadIdx.x; i < n; i += gridDim.x * blockDim.x) {
        uint32_t hi, lo;
        cvt_split2(s[2 * i], s[2 * i + 1], hi, lo);
        d_wh[off + i] = hi;
        d_wl[off + i] = lo;
    }
}

// ================= tensor-core GEMM v2: ldmatrix + pre-split weights =================
// C = act(A[M,K] @ W[N,K]^T + bias); A split on the fly; W pre-split (WH/WL).
// 3-term: Ah*Bh + Ah*Bl + Al*Bh, fp32 accum.
// act 0 none; 1 relu; 2 leakyrelu; 3 += pe[row%62][col], write C,C2 (N==128)
__global__ __launch_bounds__(256, 2)
void gemm_tc2(const float* __restrict__ A, const uint32_t* __restrict__ WH,
              const uint32_t* __restrict__ WL, const float* __restrict__ bias,
              float* __restrict__ C, float* __restrict__ C2,
              int M, int N, int K, int act)
{
    __shared__ __align__(16) uint32_t Ah_s[128 * 16];
    __shared__ __align__(16) uint32_t Al_s[128 * 16];
    __shared__ __align__(16) uint32_t Bh_s[128 * 16];
    __shared__ __align__(16) uint32_t Bl_s[128 * 16];

    int tid = threadIdx.x, lane = tid & 31, wid = tid >> 5;
    int m0 = blockIdx.x * 128, n0 = blockIdx.y * 128;
    int wm = (wid & 1) * 64, wn = (wid >> 1) * 32;    // warp tile 64x32
    int gr = lane >> 2, gc = lane & 3;
    int rl = lane & 15, chalf = lane >> 4;

    // loader mapping: row = tid>>1 (0..127), 16 k-values at offset (tid&1)*16
    int lrow = tid >> 1, lkh = tid & 1;
    int sw = (lrow & 6) >> 1;
    uint32_t sA0 = lrow * 16 + ((2 * lkh)     ^ sw) * 4;
    uint32_t sA1 = lrow * 16 + ((2 * lkh + 1) ^ sw) * 4;

    uint32_t baseAh = (uint32_t)__cvta_generic_to_shared(Ah_s);
    uint32_t baseAl = (uint32_t)__cvta_generic_to_shared(Al_s);
    uint32_t baseBh = (uint32_t)__cvta_generic_to_shared(Bh_s);
    uint32_t baseBl = (uint32_t)__cvta_generic_to_shared(Bl_s);

    float af[16];
    uint4 whr0, whr1, wlr0, wlr1;
    const uint4 z4 = make_uint4(0u, 0u, 0u, 0u);
    int KH = K >> 1;

    float acc[4][4][4];
    #pragma unroll
    for (int mt = 0; mt < 4; mt++)
        #pragma unroll
        for (int nt = 0; nt < 4; nt++)
            #pragma unroll
            for (int e = 0; e < 4; e++) acc[mt][nt][e] = 0.f;

    // prefetch tile 0
    {
        bool okA = (m0 + lrow) < M;
        const float* as = A + (size_t)(m0 + lrow) * K + lkh * 16;
        if (okA) {
            float4 v0 = *(const float4*)(as);
            float4 v1 = *(const float4*)(as + 4);
            float4 v2 = *(const float4*)(as + 8);
            float4 v3 = *(const float4*)(as + 12);
            af[0]=v0.x; af[1]=v0.y; af[2]=v0.z; af[3]=v0.w;
            af[4]=v1.x; af[5]=v1.y; af[6]=v1.z; af[7]=v1.w;
            af[8]=v2.x; af[9]=v2.y; af[10]=v2.z; af[11]=v2.w;
            af[12]=v3.x; af[13]=v3.y; af[14]=v3.z; af[15]=v3.w;
        } else {
            #pragma unroll
            for (int q = 0; q < 16; q++) af[q] = 0.f;
        }
        bool okB = (n0 + lrow) < N;
        const uint4* ph = (const uint4*)(WH + (size_t)(n0 + lrow) * KH + lkh * 8);
        const uint4* pl = (const uint4*)(WL + (size_t)(n0 + lrow) * KH + lkh * 8);
        whr0 = okB ? ph[0] : z4;  whr1 = okB ? ph[1] : z4;
        wlr0 = okB ? pl[0] : z4;  wlr1 = okB ? pl[1] : z4;
    }

    int nk = K / 32;
    for (int kt = 0; kt < nk; kt++) {
        __syncthreads();
        // convert + store A, copy W
        {
            uint32_t h[8], l[8];
            #pragma unroll
            for (int q = 0; q < 8; q++) cvt_split2(af[2*q], af[2*q+1], h[q], l[q]);
            *(uint4*)&Ah_s[sA0] = make_uint4(h[0], h[1], h[2], h[3]);
            *(uint4*)&Ah_s[sA1] = make_uint4(h[4], h[5], h[6], h[7]);
            *(uint4*)&Al_s[sA0] = make_uint4(l[0], l[1], l[2], l[3]);
            *(uint4*)&Al_s[sA1] = make_uint4(l[4], l[5], l[6], l[7]);
            *(uint4*)&Bh_s[sA0] = whr0;  *(uint4*)&Bh_s[sA1] = whr1;
            *(uint4*)&Bl_s[sA0] = wlr0;  *(uint4*)&Bl_s[sA1] = wlr1;
        }
        __syncthreads();

        if (kt + 1 < nk) {   // prefetch next tile (overlaps MMA phase)
            int k0 = (kt + 1) * 32;
            bool okA = (m0 + lrow) < M;
            const float* as = A + (size_t)(m0 + lrow) * K + k0 + lkh * 16;
            if (okA) {
                float4 v0 = *(const float4*)(as);
                float4 v1 = *(const float4*)(as + 4);
                float4 v2 = *(const float4*)(as + 8);
                float4 v3 = *(const float4*)(as + 12);
                af[0]=v0.x; af[1]=v0.y; af[2]=v0.z; af[3]=v0.w;
                af[4]=v1.x; af[5]=v1.y; af[6]=v1.z; af[7]=v1.w;
                af[8]=v2.x; af[9]=v2.y; af[10]=v2.z; af[11]=v2.w;
                af[12]=v3.x; af[13]=v3.y; af[14]=v3.z; af[15]=v3.w;
            } else {
                #pragma unroll
                for (int q = 0; q < 16; q++) af[q] = 0.f;
            }
            bool okB = (n0 + lrow) < N;
            const uint4* ph = (const uint4*)(WH + (size_t)(n0 + lrow) * KH + (k0 >> 1) + lkh * 8);
            const uint4* pl = (const uint4*)(WL + (size_t)(n0 + lrow) * KH + (k0 >> 1) + lkh * 8);
            whr0 = okB ? ph[0] : z4;  whr1 = okB ? ph[1] : z4;
            wlr0 = okB ? pl[0] : z4;  wlr1 = okB ? pl[1] : z4;
        }

        #pragma unroll
        for (int ks = 0; ks < 2; ks++) {
            uint32_t aH[4][4], aL[4][4], bH[2][4], bL[2][4];
            #pragma unroll
            for (int mt = 0; mt < 4; mt++) {
                ldsm4(aH[mt], baseAh, wm + mt * 16 + rl, ks, chalf);
                ldsm4(aL[mt], baseAl, wm + mt * 16 + rl, ks, chalf);
            }
            #pragma unroll
            for (int p = 0; p < 2; p++) {
                ldsm4(bH[p], baseBh, wn + p * 16 + rl, ks, chalf);
                ldsm4(bL[p], baseBl, wn + p * 16 + rl, ks, chalf);
            }
            #pragma unroll
            for (int mt = 0; mt < 4; mt++) {
                #pragma unroll
                for (int nti = 0; nti < 4; nti++) {
                    int ntp = nti >> 1, o = nti & 1;
                    mma16816(acc[mt][nti], aH[mt], bH[ntp][o], bH[ntp][o + 2]);
                    mma16816(acc[mt][nti], aH[mt], bL[ntp][o], bL[ntp][o + 2]);
                    mma16816(acc[mt][nti], aL[mt], bH[ntp][o], bH[ntp][o + 2]);
                }
            }
        }
    }

    // ---- epilogue ----
    #pragma unroll
    for (int mt = 0; mt < 4; mt++) {
        #pragma unroll
        for (int rr = 0; rr < 2; rr++) {
            int row = m0 + wm + mt * 16 + gr + rr * 8;
            if (row >= M) continue;
            #pragma unroll
            for (int nti = 0; nti < 4; nti++) {
                int col = n0 + wn + nti * 8 + gc * 2;
                if (col >= N) continue;
                float v0 = acc[mt][nti][rr * 2];
                float v1 = acc[mt][nti][rr * 2 + 1];
                if (bias) { v0 += bias[col]; v1 += bias[col + 1]; }
                if (act == 1) { v0 = fmaxf(v0, 0.f); v1 = fmaxf(v1, 0.f); }
                else if (act == 2) {
                    v0 = (v0 >= 0.f) ? v0 : 0.01f * v0;
                    v1 = (v1 >= 0.f) ? v1 : 0.01f * v1;
                }
                else if (act == 3) {
                    v0 += d_pe[(row % TT) * DD + (col & 127)];
                    v1 += d_pe[(row % TT) * DD + ((col + 1) & 127)];
                }
                *(float2*)(C + (size_t)row * N + col) = make_float2(v0, v1);
                if (act == 3)
                    *(float2*)(C2 + (size_t)row * N + col) = make_float2(v0, v1);
            }
        }
    }
}

// ---------------- fused pairwise bias ----------------
__global__ __launch_bounds__(256)
void bias_kernel(const float* __restrict__ E, const float* __restrict__ WB,
                 const float* __restrict__ prelu_a, int iter, float* __restrict__ OUT)
{
    __shared__ float es[VV * HDm];
    __shared__ float wb[HH * HDm];
    int bt = blockIdx.x;
    int tid = threadIdx.x;
    for (int idx = tid; idx < VV * HDm; idx += 256)
        es[idx] = E[((size_t)bt * VV) * HDm + idx];
    for (int idx = tid; idx < HH * HDm; idx += 256)
        wb[idx] = WB[idx];
    float aP = prelu_a[iter];
    __syncthreads();

    int warp = tid >> 5, lane = tid & 31;
    for (int pr = warp; pr < NPAIR; pr += 8) {
        int vi = pr / VV, vj = pr % VV;
        float acc[8] = {0,0,0,0,0,0,0,0};
        #pragma unroll
        for (int u = 0; u < 8; u++) {
            int k = u * 32 + lane;
            float hv = es[vj * HDm + k] - es[vi * HDm + k];
            hv = (hv >= 0.f) ? hv : aP * hv;
            #pragma unroll
            for (int g = 0; g < 8; g++) acc[g] += hv * wb[g * HDm + k];
        }
        #pragma unroll
        for (int g = 0; g < 8; g++)
            #pragma unroll
            for (int o = 16; o; o >>= 1)
                acc[g] += __shfl_xor_sync(0xffffffffu, acc[g], o);
        if (lane == 0) {
            float* o = OUT + (((size_t)bt * VV + vi) * VV + vj) * HH;
            #pragma unroll
            for (int g = 0; g < 8; g++) o[g] = acc[g] * 0.3535533906f;
        }
    }
}

// ---------------- graph attention (N=19, per-head bias) ----------------
__global__ __launch_bounds__(256)
void graph_attn_kernel(const float* __restrict__ QKV, const float* __restrict__ BIAS,
                       float* __restrict__ OUT)
{
    __shared__ float qs[VV * DD];
    __shared__ float ks[DD * VV];
    __shared__ float vs[DD * VV];
    int bt = blockIdx.x;
    int tid = threadIdx.x;
    for (int idx = tid; idx < VV * DD; idx += 256) {
        int n = idx >> 7, c = idx & 127;
        const float* row = QKV + (size_t)(bt * VV + n) * 384;
        qs[idx] = row[c];
        ks[c * VV + n] = row[128 + c];
        vs[c * VV + n] = row[256 + c];
    }
    __syncthreads();
    int h = tid >> 5, lane = tid & 31;
    for (int i = 0; i < VV; i++) {
        float sc = -1e30f;
        if (lane < VV) {
            float acc = 0.f;
            #pragma unroll
            for (int c = 0; c < 16; c++)
                acc += qs[i * DD + h * 16 + c] * ks[(h * 16 + c) * VV + lane];
            sc = acc * 0.25f + BIAS[(((size_t)bt * VV + i) * VV + lane) * HH + h];
        }
        float mx = sc;
        #pragma unroll
        for (int o = 16; o; o >>= 1) mx = fmaxf(mx, __shfl_xor_sync(0xffffffffu, mx, o));
        float ev = (lane < VV) ? __expf(sc - mx) : 0.f;
        float sum = ev;
        #pragma unroll
        for (int o = 16; o; o >>= 1) sum += __shfl_xor_sync(0xffffffffu, sum, o);
        float aj = ev / sum;
        float o_acc = 0.f;
        int cc = lane & 15;
        #pragma unroll
        for (int j = 0; j < VV; j++) {
            float aw = __shfl_sync(0xffffffffu, aj, j);
            o_acc += aw * vs[(h * 16 + cc) * VV + j];
        }
        if (lane < 16) OUT[(size_t)(bt * VV + i) * DD + h * 16 + lane] = o_acc;
    }
}

// ---------------- temporal attention (N=62, no bias) ----------------
__global__ __launch_bounds__(128)
void temporal_attn_kernel(const float* __restrict__ QKV, float* __restrict__ OUT)
{
    __shared__ float ks[16 * 65];
    __shared__ float vs[16 * 65];
    int bn = blockIdx.x, h = blockIdx.y;
    int tid = threadIdx.x;
    for (int idx = tid; idx < 16 * 64; idx += 128) {
        int c = idx >> 6, n = idx & 63;
        float kv = 0.f, vv = 0.f;
        if (n < TT) {
            const float* row = QKV + (size_t)(bn * TT + n) * 384 + h * 16 + c;
            kv = row[128];
            vv = row[256];
        }
        ks[c * 65 + n] = kv;
        vs[c * 65 + n] = vv;
    }
    __syncthreads();
    int warp = tid >> 5, lane = tid & 31;
    for (int i = warp; i < TT; i += 4) {
        float q = (lane < 16) ? QKV[(size_t)(bn * TT + i) * 384 + h * 16 + lane] : 0.f;
        float s0 = 0.f, s1 = 0.f;
        #pragma unroll
        for (int c = 0; c < 16; c++) {
            float qc = __shfl_sync(0xffffffffu, q, c);
            s0 += qc * ks[c * 65 + lane];
            s1 += qc * ks[c * 65 + lane + 32];
        }
        s0 *= 0.25f; s1 *= 0.25f;
        bool v1 = (lane + 32) < TT;
        float mx = fmaxf(s0, v1 ? s1 : -1e30f);
        #pragma unroll
        for (int o = 16; o; o >>= 1) mx = fmaxf(mx, __shfl_xor_sync(0xffffffffu, mx, o));
        float e0 = __expf(s0 - mx);
        float e1 = v1 ? __expf(s1 - mx) : 0.f;
        float sum = e0 + e1;
        #pragma unroll
        for (int o = 16; o; o >>= 1) sum += __shfl_xor_sync(0xffffffffu, sum, o);
        float inv = 1.f / sum;
        e0 *= inv; e1 *= inv;
        float o_acc = 0.f;
        int cc = lane & 15;
        #pragma unroll
        for (int j = 0; j < 32; j++) {
            float aw = __shfl_sync(0xffffffffu, e0, j);
            o_acc += aw * vs[cc * 65 + j];
        }
        #pragma unroll
        for (int j = 32; j < TT; j++) {
            float aw = __shfl_sync(0xffffffffu, e1, j - 32);
            o_acc += aw * vs[cc * 65 + j];
        }
        if (lane < 16) OUT[(size_t)(bn * TT + i) * DD + h * 16 + lane] = o_acc;
    }
}

// ---------------- LayerNorm: out = LN(X + R) * g + b (+ ADD) ----------------
__global__ __launch_bounds__(256)
void ln_kernel(const float* __restrict__ X, const float* __restrict__ R,
               const float* __restrict__ g, const float* __restrict__ b,
               float* __restrict__ OUT, const float* __restrict__ ADD)
{
    int warp = threadIdx.x >> 5, lane = threadIdx.x & 31;
    int row = blockIdx.x * 8 + warp;
    if (row >= NTOK) return;
    const float* x = X + (size_t)row * DD;
    const float* r = R + (size_t)row * DD;
    float v[4];
    #pragma unroll
    for (int u = 0; u < 4; u++) v[u] = x[lane + u * 32] + r[lane + u * 32];
    float s = v[0] + v[1] + v[2] + v[3];
    #pragma unroll
    for (int o = 16; o; o >>= 1) s += __shfl_xor_sync(0xffffffffu, s, o);
    float m = s * (1.f / 128.f);
    float sv = 0.f;
    #pragma unroll
    for (int u = 0; u < 4; u++) { float dlt = v[u] - m; sv += dlt * dlt; }
    #pragma unroll
    for (int o = 16; o; o >>= 1) sv += __shfl_xor_sync(0xffffffffu, sv, o);
    float rinv = rsqrtf(sv * (1.f / 128.f) + 1e-5f);
    #pragma unroll
    for (int u = 0; u < 4; u++) {
        int c = lane + u * 32;
        float o = (v[u] - m) * rinv * g[c] + b[c];
        if (ADD) o += ADD[(size_t)row * DD + c];
        OUT[(size_t)row * DD + c] = o;
    }
}

// ---------------- host launcher ----------------
static void GEMM(const float* A, const uint32_t* WH, const uint32_t* WL,
                 const float* bias, float* C, int M, int N, int K, int act,
                 float* C2 = nullptr)
{
    dim3 grid((M + 127) / 128, (N + 127) / 128);
    gemm_tc2<<<grid, 256>>>(A, WH, WL, bias, C, C2, M, N, K, act);
}

extern "C" void kernel_launch(void* const* d_in, const int* in_sizes, int n_in,
                              void* d_out, int out_size)
{
    const float* pose    = (const float*)d_in[0];
    const float* W_pose  = (const float*)d_in[1];
    const float* W_emb   = (const float*)d_in[2];
    const float* prelu_a = (const float*)d_in[3];
    const float* W_bias  = (const float*)d_in[4];
    const float* gWqkv   = (const float*)d_in[5];
    const float* gbqkv   = (const float*)d_in[6];
    const float* gWo     = (const float*)d_in[7];
    const float* gbo     = (const float*)d_in[8];
    const float* gln1g   = (const float*)d_in[9];
    const float* gln1b   = (const float*)d_in[10];
    const float* gW1     = (const float*)d_in[11];
    const float* gb1     = (const float*)d_in[12];
    const float* gW2     = (const float*)d_in[13];
    const float* gb2     = (const float*)d_in[14];
    const float* gln2g   = (const float*)d_in[15];
    const float* gln2b   = (const float*)d_in[16];
    const float* deW     = (const float*)d_in[17];
    const float* deb     = (const float*)d_in[18];
    const float* tWqkv   = (const float*)d_in[19];
    const float* tbqkv   = (const float*)d_in[20];
    const float* tWo     = (const float*)d_in[21];
    const float* tbo     = (const float*)d_in[22];
    const float* tln1g   = (const float*)d_in[23];
    const float* tln1b   = (const float*)d_in[24];
    const float* tW1     = (const float*)d_in[25];
    const float* tb1     = (const float*)d_in[26];
    const float* tW2     = (const float*)d_in[27];
    const float* tb2     = (const float*)d_in[28];
    const float* tln2g   = (const float*)d_in[29];
    const float* tln2b   = (const float*)d_in[30];
    const float* W_out   = (const float*)d_in[31];
    float* out = (float*)d_out;

    float *p_, *y_, *e_, *bias_, *qkv_, *a_, *y1_, *h_, *f_, *mem_;
    uint32_t *wh_, *wl_;
    cudaGetSymbolAddress((void**)&p_,    d_p);
    cudaGetSymbolAddress((void**)&y_,    d_y);
    cudaGetSymbolAddress((void**)&e_,    d_e);
    cudaGetSymbolAddress((void**)&bias_, d_bias);
    cudaGetSymbolAddress((void**)&qkv_,  d_qkv);
    cudaGetSymbolAddress((void**)&a_,    d_a);
    cudaGetSymbolAddress((void**)&y1_,   d_y1);
    cudaGetSymbolAddress((void**)&h_,    d_h);
    cudaGetSymbolAddress((void**)&f_,    d_f);
    cudaGetSymbolAddress((void**)&mem_,  d_mem);
    cudaGetSymbolAddress((void**)&wh_,   d_wh);
    cudaGetSymbolAddress((void**)&wl_,   d_wl);

    // weight split offsets (u32 units)
    const int oWpose = 0;                 // 2048
    const int oWemb  = 2048;              // 2x4096
    const int oGqkv  = 10240;             // 2x24576
    const int oGWo   = 59392;             // 2x8192
    const int oGW1   = 75776;             // 2x16384
    const int oGW2   = 108544;            // 2x16384
    const int oDeW   = 141312;            // 2x8192
    const int oTqkv  = 157696;            // 2x24576
    const int oTWo   = 206848;            // 2x8192
    const int oTW1   = 223232;            // 2x16384
    const int oTW2   = 256000;            // 2x16384
    const int oWout  = 288768;            // 4096

    PrepList pl;
    int wi = 0;
    auto addw = [&](const float* s, int off, int n) {
        pl.src[wi] = s; pl.off[wi] = off; pl.n[wi] = n; wi++;
    };
    addw(W_pose, oWpose, 2048);
    addw(W_emb,               oWemb,        4096);
    addw(W_emb + 8192,        oWemb + 4096, 4096);
    addw(gWqkv,               oGqkv,          24576);
    addw(gWqkv + 49152,       oGqkv + 24576,  24576);
    addw(gWo,                 oGWo,           8192);
    addw(gWo + 16384,         oGWo + 8192,    8192);
    addw(gW1,                 oGW1,           16384);
    addw(gW1 + 32768,         oGW1 + 16384,   16384);
    addw(gW2,                 oGW2,           16384);
    addw(gW2 + 32768,         oGW2 + 16384,   16384);
    addw(deW,                 oDeW,           8192);
    addw(deW + 16384,         oDeW + 8192,    8192);
    addw(tWqkv,               oTqkv,          24576);
    addw(tWqkv + 49152,       oTqkv + 24576,  24576);
    addw(tWo,                 oTWo,           8192);
    addw(tWo + 16384,         oTWo + 8192,    8192);
    addw(tW1,                 oTW1,           16384);
    addw(tW1 + 32768,         oTW1 + 16384,   16384);
    addw(tW2,                 oTW2,           16384);
    addw(tW2 + 32768,         oTW2 + 16384,   16384);
    addw(W_out, oWout, 4096);

    split_weights_kernel<<<dim3(48, NW), 256>>>(pl);
    build_p_kernel<<<(NTOK * CC + 255) / 256, 256>>>(pose);
    build_pe_kernel<<<TT, DD>>>();

    GEMM(p_, wh_ + oWpose, wl_ + oWpose, nullptr, y_, NTOK, 128, 32, 0);

    for (int it = 0; it < 2; it++) {
        GEMM(p_, wh_ + oWemb + it * 4096, wl_ + oWemb + it * 4096, nullptr, e_,
             NTOK, 256, 32, 0);
        bias_kernel<<<NBT, 256>>>(e_, W_bias + (size_t)it * HH * HDm, prelu_a, it, bias_);

        // ---- graph encoder block ----
        GEMM(y_, wh_ + oGqkv + it * 24576, wl_ + oGqkv + it * 24576,
             gbqkv + (size_t)it * 3 * DD, qkv_, NTOK, 384, 128, 0);
        graph_attn_kernel<<<NBT, 256>>>(qkv_, bias_, a_);
        GEMM(a_, wh_ + oGWo + it * 8192, wl_ + oGWo + it * 8192,
             gbo + (size_t)it * DD, f_, NTOK, 128, 128, 0);
        ln_kernel<<<(NTOK + 7) / 8, 256>>>(f_, y_, gln1g + it * DD, gln1b + it * DD, y1_, nullptr);
        GEMM(y1_, wh_ + oGW1 + it * 16384, wl_ + oGW1 + it * 16384,
             gb1 + (size_t)it * HDm, h_, NTOK, 256, 128, 1);
        GEMM(h_, wh_ + oGW2 + it * 16384, wl_ + oGW2 + it * 16384,
             gb2 + (size_t)it * DD, f_, NTOK, 128, 256, 0);
        ln_kernel<<<(NTOK + 7) / 8, 256>>>(f_, y1_, gln2g + it * DD, gln2b + it * DD, a_, nullptr);
        GEMM(a_, wh_ + oDeW + it * 8192, wl_ + oDeW + it * 8192,
             deb + (size_t)it * DD, y_, NTOK, 128, 128, 3, mem_);

        // ---- temporal encoder block ----
        GEMM(y_, wh_ + oTqkv + it * 24576, wl_ + oTqkv + it * 24576,
             tbqkv + (size_t)it * 3 * DD, qkv_, NTOK, 384, 128, 0);
        {
            dim3 grid(BB * VV, HH);
            temporal_attn_kernel<<<grid, 128>>>(qkv_, a_);
        }
        GEMM(a_, wh_ + oTWo + it * 8192, wl_ + oTWo + it * 8192,
             tbo + (size_t)it * DD, f_, NTOK, 128, 128, 0);
        ln_kernel<<<(NTOK + 7) / 8, 256>>>(f_, y_, tln1g + it * DD, tln1b + it * DD, y1_, nullptr);
        GEMM(y1_, wh_ + oTW1 + it * 16384, wl_ + oTW1 + it * 16384,
             tb1 + (size_t)it * HDm, h_, NTOK, 256, 128, 1);
        GEMM(h_, wh_ + oTW2 + it * 16384, wl_ + oTW2 + it * 16384,
             tb2 + (size_t)it * DD, f_, NTOK, 128, 256, 0);
        ln_kernel<<<(NTOK + 7) / 8, 256>>>(f_, y1_, tln2g + it * DD, tln2b + it * DD, y_, mem_);
    }

    // out = leakyrelu(y @ W_out^T)
    GEMM(y_, wh_ + oWout, wl_ + oWout, nullptr, out, NTOK, 64, 128, 2);
}

// round 11
// speedup vs baseline: 1.7381x; 1.0563x over previous
#include <cuda_runtime.h>
#include <cuda_bf16.h>
#include <math.h>
#include <stdint.h>

// Problem constants
#define BB   16
#define CC   32
#define TT   62
#define VV   19
#define DD   128
#define HH   8
#define HDm  256
#define NBT  (BB*TT)      // 992
#define NTOK (NBT*VV)     // 18848
#define NPAIR (VV*VV)     // 361

// ---------------- scratch buffers ----------------
__device__ float d_p   [NTOK*CC];
__device__ float d_y   [NTOK*DD];
__device__ float d_e   [NTOK*HDm];
__device__ float d_bias[NBT*NPAIR*HH];
__device__ float d_qkv [NTOK*384];
__device__ float d_a   [NTOK*DD];
__device__ float d_y1  [NTOK*DD];
__device__ float d_h   [NTOK*HDm];
__device__ float d_f   [NTOK*DD];
__device__ float d_mem [NTOK*DD];
__device__ float d_pe  [TT*DD];
// pre-split weights (bf16 hi/lo packed as u32 = 2 bf16)
#define WTOT 292864
__device__ uint32_t d_wh[WTOT];
__device__ uint32_t d_wl[WTOT];

// ---------------- helpers ----------------
__device__ __forceinline__ void cvt_split2(float x, float y, uint32_t& hi, uint32_t& lo) {
    __nv_bfloat16 xh = __float2bfloat16(x);
    __nv_bfloat16 yh = __float2bfloat16(y);
    __nv_bfloat16 xl = __float2bfloat16(x - __bfloat162float(xh));
    __nv_bfloat16 yl = __float2bfloat16(y - __bfloat162float(yh));
    hi = ((uint32_t)__bfloat16_as_ushort(yh) << 16) | (uint32_t)__bfloat16_as_ushort(xh);
    lo = ((uint32_t)__bfloat16_as_ushort(yl) << 16) | (uint32_t)__bfloat16_as_ushort(xl);
}

__device__ __forceinline__ void mma16816(float (&c)[4], const uint32_t (&a)[4],
                                         uint32_t b0, uint32_t b1) {
    asm volatile(
        "mma.sync.aligned.m16n8k16.row.col.f32.bf16.bf16.f32 "
        "{%0,%1,%2,%3}, {%4,%5,%6,%7}, {%8,%9}, {%0,%1,%2,%3};"
        : "+f"(c[0]), "+f"(c[1]), "+f"(c[2]), "+f"(c[3])
        : "r"(a[0]), "r"(a[1]), "r"(a[2]), "r"(a[3]), "r"(b0), "r"(b1));
}

__device__ __forceinline__ void ldsm4(uint32_t (&r)[4], uint32_t base, int row, int ks, int chalf) {
    int chunk = 2 * ks + chalf;
    int cp = chunk ^ ((row & 6) >> 1);
    uint32_t addr = base + (uint32_t)(row * 64 + cp * 16);
    asm volatile("ldmatrix.sync.aligned.m8n8.x4.shared.b16 {%0,%1,%2,%3}, [%4];"
        : "=r"(r[0]), "=r"(r[1]), "=r"(r[2]), "=r"(r[3]) : "r"(addr));
}

// ---------------- p builder ----------------
__global__ void build_p_kernel(const float* __restrict__ pose) {
    int idx = blockIdx.x * 256 + threadIdx.x;
    if (idx >= NTOK * CC) return;
    int c  = idx & 31;
    int v  = (idx >> 5) % VV;
    int bt = idx / (CC * VV);
    int b = bt / TT, t = bt % TT;
    d_p[idx] = pose[(((size_t)b * CC + c) * TT + t) * VV + v];
}

// ---------------- positional encoding ----------------
__global__ void build_pe_kernel() {
    int t = blockIdx.x, c = threadIdx.x;
    int i2 = c & ~1;
    float div = expf((float)i2 * (-9.210340371976184f / 128.f));
    float ang = (float)t * div;
    d_pe[t * DD + c] = (c & 1) ? cosf(ang) : sinf(ang);
}

// ---------------- weight pre-split ----------------
#define NW 22
struct PrepList {
    const float* src[NW];
    int off[NW];
    int n[NW];
};
__global__ void split_weights_kernel(PrepList pl) {
    int wi = blockIdx.y;
    const float* s = pl.src[wi];
    int off = pl.off[wi], n = pl.n[wi];
    for (int i = blockIdx.x * blockDim.x + threadIdx.x; i < n; i += gridDim.x * blockDim.x) {
        uint32_t hi, lo;
        cvt_split2(s[2 * i], s[2 * i + 1], hi, lo);
        d_wh[off + i] = hi;
        d_wl[off + i] = lo;
    }
}

// ================= tensor-core GEMM v3: 64x128 tiles, double-buffered =================
// C = act(A[M,K] @ W[N,K]^T + bias); A split on the fly; W pre-split (WH/WL).
// 3-term: Ah*Bh + Ah*Bl + Al*Bh, fp32 accum.
// act 0 none; 1 relu; 2 leakyrelu; 3 += pe[row%62][col], write C,C2 (N==128)
__global__ __launch_bounds__(256, 2)
void gemm_tc3(const float* __restrict__ A, const uint32_t* __restrict__ WH,
              const uint32_t* __restrict__ WL, const float* __restrict__ bias,
              float* __restrict__ C, float* __restrict__ C2,
              int M, int N, int K, int act)
{
    __shared__ __align__(16) uint32_t Ah_s[2][64 * 16];
    __shared__ __align__(16) uint32_t Al_s[2][64 * 16];
    __shared__ __align__(16) uint32_t Bh_s[2][128 * 16];
    __shared__ __align__(16) uint32_t Bl_s[2][128 * 16];

    int tid = threadIdx.x, lane = tid & 31, wid = tid >> 5;
    int m0 = blockIdx.x * 64, n0 = blockIdx.y * 128;
    int wm = (wid & 1) * 32, wn = (wid >> 1) * 32;    // warp tile 32x32
    int gr = lane >> 2, gc = lane & 3;
    int rl = lane & 15, chalf = lane >> 4;

    // A loader: row = tid>>2 (0..63), q = tid&3 -> 8 floats at k = q*8
    int arow = tid >> 2, aq = tid & 3;
    int acp = aq ^ ((arow & 6) >> 1);
    uint32_t aoff = (uint32_t)(arow * 16 + acp * 4);
    // B loader: row = tid>>1 (0..127), two uint4 chunks c0 = 2*(tid&1)
    int brow = tid >> 1, bq = tid & 1;
    int bsw = (brow & 6) >> 1;
    uint32_t boff0 = (uint32_t)(brow * 16 + ((2 * bq)     ^ bsw) * 4);
    uint32_t boff1 = (uint32_t)(brow * 16 + ((2 * bq + 1) ^ bsw) * 4);

    float af[8];
    uint4 whr0, whr1, wlr0, wlr1;
    const uint4 z4 = make_uint4(0u, 0u, 0u, 0u);
    int KH = K >> 1;
    bool okA = (m0 + arow) < M;
    bool okB = (n0 + brow) < N;
    const float* aptr = A + (size_t)(m0 + arow) * K + aq * 8;
    const uint4* bhp = (const uint4*)(WH + (size_t)(n0 + brow) * KH + bq * 8);
    const uint4* blp = (const uint4*)(WL + (size_t)(n0 + brow) * KH + bq * 8);

    float acc[2][4][4];
    #pragma unroll
    for (int mt = 0; mt < 2; mt++)
        #pragma unroll
        for (int nt = 0; nt < 4; nt++)
            #pragma unroll
            for (int e = 0; e < 4; e++) acc[mt][nt][e] = 0.f;

    // ---- prologue: tile 0 into stage 0 ----
    {
        #pragma unroll
        for (int q = 0; q < 8; q++) af[q] = 0.f;
        if (okA) {
            float4 v0 = *(const float4*)(aptr);
            float4 v1 = *(const float4*)(aptr + 4);
            af[0]=v0.x; af[1]=v0.y; af[2]=v0.z; af[3]=v0.w;
            af[4]=v1.x; af[5]=v1.y; af[6]=v1.z; af[7]=v1.w;
        }
        whr0 = okB ? bhp[0] : z4;  whr1 = okB ? bhp[1] : z4;
        wlr0 = okB ? blp[0] : z4;  wlr1 = okB ? blp[1] : z4;
        uint32_t h[4], l[4];
        #pragma unroll
        for (int q = 0; q < 4; q++) cvt_split2(af[2*q], af[2*q+1], h[q], l[q]);
        *(uint4*)&Ah_s[0][aoff] = make_uint4(h[0], h[1], h[2], h[3]);
        *(uint4*)&Al_s[0][aoff] = make_uint4(l[0], l[1], l[2], l[3]);
        *(uint4*)&Bh_s[0][boff0] = whr0;  *(uint4*)&Bh_s[0][boff1] = whr1;
        *(uint4*)&Bl_s[0][boff0] = wlr0;  *(uint4*)&Bl_s[0][boff1] = wlr1;
    }
    __syncthreads();

    int nk = K / 32;
    for (int kt = 0; kt < nk; kt++) {
        int cur = kt & 1;
        if (kt + 1 < nk) {   // prefetch next tile into registers (overlaps MMA)
            int k0 = (kt + 1) * 32;
            if (okA) {
                const float* as = aptr + k0;
                float4 v0 = *(const float4*)(as);
                float4 v1 = *(const float4*)(as + 4);
                af[0]=v0.x; af[1]=v0.y; af[2]=v0.z; af[3]=v0.w;
                af[4]=v1.x; af[5]=v1.y; af[6]=v1.z; af[7]=v1.w;
            }
            const uint4* ph = bhp + (k0 >> 3);
            const uint4* pl = blp + (k0 >> 3);
            whr0 = okB ? ph[0] : z4;  whr1 = okB ? ph[1] : z4;
            wlr0 = okB ? pl[0] : z4;  wlr1 = okB ? pl[1] : z4;
        }

        uint32_t baseAh = (uint32_t)__cvta_generic_to_shared(&Ah_s[cur][0]);
        uint32_t baseAl = (uint32_t)__cvta_generic_to_shared(&Al_s[cur][0]);
        uint32_t baseBh = (uint32_t)__cvta_generic_to_shared(&Bh_s[cur][0]);
        uint32_t baseBl = (uint32_t)__cvta_generic_to_shared(&Bl_s[cur][0]);

        #pragma unroll
        for (int ks = 0; ks < 2; ks++) {
            uint32_t aH[2][4], aL[2][4], bH[2][4], bL[2][4];
            // stage 1: hi*hi
            #pragma unroll
            for (int mt = 0; mt < 2; mt++) ldsm4(aH[mt], baseAh, wm + mt * 16 + rl, ks, chalf);
            #pragma unroll
            for (int p = 0; p < 2; p++)    ldsm4(bH[p],  baseBh, wn + p * 16 + rl, ks, chalf);
            #pragma unroll
            for (int mt = 0; mt < 2; mt++)
                #pragma unroll
                for (int nti = 0; nti < 4; nti++) {
                    int ntp = nti >> 1, o = nti & 1;
                    mma16816(acc[mt][nti], aH[mt], bH[ntp][o], bH[ntp][o + 2]);
                }
            // stage 2: hi*lo
            #pragma unroll
            for (int p = 0; p < 2; p++)    ldsm4(bL[p],  baseBl, wn + p * 16 + rl, ks, chalf);
            #pragma unroll
            for (int mt = 0; mt < 2; mt++)
                #pragma unroll
                for (int nti = 0; nti < 4; nti++) {
                    int ntp = nti >> 1, o = nti & 1;
                    mma16816(acc[mt][nti], aH[mt], bL[ntp][o], bL[ntp][o + 2]);
                }
            // stage 3: lo*hi
            #pragma unroll
            for (int mt = 0; mt < 2; mt++) ldsm4(aL[mt], baseAl, wm + mt * 16 + rl, ks, chalf);
            #pragma unroll
            for (int mt = 0; mt < 2; mt++)
                #pragma unroll
                for (int nti = 0; nti < 4; nti++) {
                    int ntp = nti >> 1, o = nti & 1;
                    mma16816(acc[mt][nti], aL[mt], bH[ntp][o], bH[ntp][o + 2]);
                }
        }

        if (kt + 1 < nk) {
            int nb = cur ^ 1;
            uint32_t h[4], l[4];
            #pragma unroll
            for (int q = 0; q < 4; q++) cvt_split2(af[2*q], af[2*q+1], h[q], l[q]);
            *(uint4*)&Ah_s[nb][aoff] = make_uint4(h[0], h[1], h[2], h[3]);
            *(uint4*)&Al_s[nb][aoff] = make_uint4(l[0], l[1], l[2], l[3]);
            *(uint4*)&Bh_s[nb][boff0] = whr0;  *(uint4*)&Bh_s[nb][boff1] = whr1;
            *(uint4*)&Bl_s[nb][boff0] = wlr0;  *(uint4*)&Bl_s[nb][boff1] = wlr1;
            __syncthreads();
        }
    }

    // ---- epilogue ----
    #pragma unroll
    for (int mt = 0; mt < 2; mt++) {
        #pragma unroll
        for (int rr = 0; rr < 2; rr++) {
            int row = m0 + wm + mt * 16 + gr + rr * 8;
            if (row >= M) continue;
            #pragma unroll
            for (int nti = 0; nti < 4; nti++) {
                int col = n0 + wn + nti * 8 + gc * 2;
                if (col >= N) continue;
                float v0 = acc[mt][nti][rr * 2];
                float v1 = acc[mt][nti][rr * 2 + 1];
                if (bias) { v0 += bias[col]; v1 += bias[col + 1]; }
                if (act == 1) { v0 = fmaxf(v0, 0.f); v1 = fmaxf(v1, 0.f); }
                else if (act == 2) {
                    v0 = (v0 >= 0.f) ? v0 : 0.01f * v0;
                    v1 = (v1 >= 0.f) ? v1 : 0.01f * v1;
                }
                else if (act == 3) {
                    v0 += d_pe[(row % TT) * DD + (col & 127)];
                    v1 += d_pe[(row % TT) * DD + ((col + 1) & 127)];
                }
                *(float2*)(C + (size_t)row * N + col) = make_float2(v0, v1);
                if (act == 3)
                    *(float2*)(C2 + (size_t)row * N + col) = make_float2(v0, v1);
            }
        }
    }
}

// ---------------- fused pairwise bias ----------------
__global__ __launch_bounds__(256)
void bias_kernel(const float* __restrict__ E, const float* __restrict__ WB,
                 const float* __restrict__ prelu_a, int iter, float* __restrict__ OUT)
{
    __shared__ float es[VV * HDm];
    __shared__ float wb[HH * HDm];
    int bt = blockIdx.x;
    int tid = threadIdx.x;
    for (int idx = tid; idx < VV * HDm; idx += 256)
        es[idx] = E[((size_t)bt * VV) * HDm + idx];
    for (int idx = tid; idx < HH * HDm; idx += 256)
        wb[idx] = WB[idx];
    float aP = prelu_a[iter];
    __syncthreads();

    int warp = tid >> 5, lane = tid & 31;
    for (int pr = warp; pr < NPAIR; pr += 8) {
        int vi = pr / VV, vj = pr % VV;
        float acc[8] = {0,0,0,0,0,0,0,0};
        #pragma unroll
        for (int u = 0; u < 8; u++) {
            int k = u * 32 + lane;
            float hv = es[vj * HDm + k] - es[vi * HDm + k];
            hv = (hv >= 0.f) ? hv : aP * hv;
            #pragma unroll
            for (int g = 0; g < 8; g++) acc[g] += hv * wb[g * HDm + k];
        }
        #pragma unroll
        for (int g = 0; g < 8; g++)
            #pragma unroll
            for (int o = 16; o; o >>= 1)
                acc[g] += __shfl_xor_sync(0xffffffffu, acc[g], o);
        if (lane == 0) {
            float* o = OUT + (((size_t)bt * VV + vi) * VV + vj) * HH;
            #pragma unroll
            for (int g = 0; g < 8; g++) o[g] = acc[g] * 0.3535533906f;
        }
    }
}

// ---------------- graph attention (N=19, per-head bias) ----------------
__global__ __launch_bounds__(256)
void graph_attn_kernel(const float* __restrict__ QKV, const float* __restrict__ BIAS,
                       float* __restrict__ OUT)
{
    __shared__ float qs[VV * DD];
    __shared__ float ks[DD * VV];
    __shared__ float vs[DD * VV];
    int bt = blockIdx.x;
    int tid = threadIdx.x;
    for (int idx = tid; idx < VV * DD; idx += 256) {
        int n = idx >> 7, c = idx & 127;
        const float* row = QKV + (size_t)(bt * VV + n) * 384;
        qs[idx] = row[c];
        ks[c * VV + n] = row[128 + c];
        vs[c * VV + n] = row[256 + c];
    }
    __syncthreads();
    int h = tid >> 5, lane = tid & 31;
    for (int i = 0; i < VV; i++) {
        float sc = -1e30f;
        if (lane < VV) {
            float acc = 0.f;
            #pragma unroll
            for (int c = 0; c < 16; c++)
                acc += qs[i * DD + h * 16 + c] * ks[(h * 16 + c) * VV + lane];
            sc = acc * 0.25f + BIAS[(((size_t)bt * VV + i) * VV + lane) * HH + h];
        }
        float mx = sc;
        #pragma unroll
        for (int o = 16; o; o >>= 1) mx = fmaxf(mx, __shfl_xor_sync(0xffffffffu, mx, o));
        float ev = (lane < VV) ? __expf(sc - mx) : 0.f;
        float sum = ev;
        #pragma unroll
        for (int o = 16; o; o >>= 1) sum += __shfl_xor_sync(0xffffffffu, sum, o);
        float aj = ev / sum;
        float o_acc = 0.f;
        int cc = lane & 15;
        #pragma unroll
        for (int j = 0; j < VV; j++) {
            float aw = __shfl_sync(0xffffffffu, aj, j);
            o_acc += aw * vs[(h * 16 + cc) * VV + j];
        }
        if (lane < 16) OUT[(size_t)(bt * VV + i) * DD + h * 16 + lane] = o_acc;
    }
}

// ---------------- temporal attention (N=62, no bias) ----------------
__global__ __launch_bounds__(128)
void temporal_attn_kernel(const float* __restrict__ QKV, float* __restrict__ OUT)
{
    __shared__ float ks[16 * 65];
    __shared__ float vs[16 * 65];
    int bn = blockIdx.x, h = blockIdx.y;
    int tid = threadIdx.x;
    for (int idx = tid; idx < 16 * 64; idx += 128) {
        int c = idx >> 6, n = idx & 63;
        float kv = 0.f, vv = 0.f;
        if (n < TT) {
            const float* row = QKV + (size_t)(bn * TT + n) * 384 + h * 16 + c;
            kv = row[128];
            vv = row[256];
        }
        ks[c * 65 + n] = kv;
        vs[c * 65 + n] = vv;
    }
    __syncthreads();
    int warp = tid >> 5, lane = tid & 31;
    for (int i = warp; i < TT; i += 4) {
        float q = (lane < 16) ? QKV[(size_t)(bn * TT + i) * 384 + h * 16 + lane] : 0.f;
        float s0 = 0.f, s1 = 0.f;
        #pragma unroll
        for (int c = 0; c < 16; c++) {
            float qc = __shfl_sync(0xffffffffu, q, c);
            s0 += qc * ks[c * 65 + lane];
            s1 += qc * ks[c * 65 + lane + 32];
        }
        s0 *= 0.25f; s1 *= 0.25f;
        bool v1 = (lane + 32) < TT;
        float mx = fmaxf(s0, v1 ? s1 : -1e30f);
        #pragma unroll
        for (int o = 16; o; o >>= 1) mx = fmaxf(mx, __shfl_xor_sync(0xffffffffu, mx, o));
        float e0 = __expf(s0 - mx);
        float e1 = v1 ? __expf(s1 - mx) : 0.f;
        float sum = e0 + e1;
        #pragma unroll
        for (int o = 16; o; o >>= 1) sum += __shfl_xor_sync(0xffffffffu, sum, o);
        float inv = 1.f / sum;
        e0 *= inv; e1 *= inv;
        float o_acc = 0.f;
        int cc = lane & 15;
        #pragma unroll
        for (int j = 0; j < 32; j++) {
            float aw = __shfl_sync(0xffffffffu, e0, j);
            o_acc += aw * vs[cc * 65 + j];
        }
        #pragma unroll
        for (int j = 32; j < TT; j++) {
            float aw = __shfl_sync(0xffffffffu, e1, j - 32);
            o_acc += aw * vs[cc * 65 + j];
        }
        if (lane < 16) OUT[(size_t)(bn * TT + i) * DD + h * 16 + lane] = o_acc;
    }
}

// ---------------- LayerNorm: out = LN(X + R) * g + b (+ ADD) ----------------
__global__ __launch_bounds__(256)
void ln_kernel(const float* __restrict__ X, const float* __restrict__ R,
               const float* __restrict__ g, const float* __restrict__ b,
               float* __restrict__ OUT, const float* __restrict__ ADD)
{
    int warp = threadIdx.x >> 5, lane = threadIdx.x & 31;
    int row = blockIdx.x * 8 + warp;
    if (row >= NTOK) return;
    const float* x = X + (size_t)row * DD;
    const float* r = R + (size_t)row * DD;
    float v[4];
    #pragma unroll
    for (int u = 0; u < 4; u++) v[u] = x[lane + u * 32] + r[lane + u * 32];
    float s = v[0] + v[1] + v[2] + v[3];
    #pragma unroll
    for (int o = 16; o; o >>= 1) s += __shfl_xor_sync(0xffffffffu, s, o);
    float m = s * (1.f / 128.f);
    float sv = 0.f;
    #pragma unroll
    for (int u = 0; u < 4; u++) { float dlt = v[u] - m; sv += dlt * dlt; }
    #pragma unroll
    for (int o = 16; o; o >>= 1) sv += __shfl_xor_sync(0xffffffffu, sv, o);
    float rinv = rsqrtf(sv * (1.f / 128.f) + 1e-5f);
    #pragma unroll
    for (int u = 0; u < 4; u++) {
        int c = lane + u * 32;
        float o = (v[u] - m) * rinv * g[c] + b[c];
        if (ADD) o += ADD[(size_t)row * DD + c];
        OUT[(size_t)row * DD + c] = o;
    }
}

// ---------------- host launcher ----------------
static void GEMM(const float* A, const uint32_t* WH, const uint32_t* WL,
                 const float* bias, float* C, int M, int N, int K, int act,
                 float* C2 = nullptr)
{
    dim3 grid((M + 63) / 64, (N + 127) / 128);
    gemm_tc3<<<grid, 256>>>(A, WH, WL, bias, C, C2, M, N, K, act);
}

extern "C" void kernel_launch(void* const* d_in, const int* in_sizes, int n_in,
                              void* d_out, int out_size)
{
    const float* pose    = (const float*)d_in[0];
    const float* W_pose  = (const float*)d_in[1];
    const float* W_emb   = (const float*)d_in[2];
    const float* prelu_a = (const float*)d_in[3];
    const float* W_bias  = (const float*)d_in[4];
    const float* gWqkv   = (const float*)d_in[5];
    const float* gbqkv   = (const float*)d_in[6];
    const float* gWo     = (const float*)d_in[7];
    const float* gbo     = (const float*)d_in[8];
    const float* gln1g   = (const float*)d_in[9];
    const float* gln1b   = (const float*)d_in[10];
    const float* gW1     = (const float*)d_in[11];
    const float* gb1     = (const float*)d_in[12];
    const float* gW2     = (const float*)d_in[13];
    const float* gb2     = (const float*)d_in[14];
    const float* gln2g   = (const float*)d_in[15];
    const float* gln2b   = (const float*)d_in[16];
    const float* deW     = (const float*)d_in[17];
    const float* deb     = (const float*)d_in[18];
    const float* tWqkv   = (const float*)d_in[19];
    const float* tbqkv   = (const float*)d_in[20];
    const float* tWo     = (const float*)d_in[21];
    const float* tbo     = (const float*)d_in[22];
    const float* tln1g   = (const float*)d_in[23];
    const float* tln1b   = (const float*)d_in[24];
    const float* tW1     = (const float*)d_in[25];
    const float* tb1     = (const float*)d_in[26];
    const float* tW2     = (const float*)d_in[27];
    const float* tb2     = (const float*)d_in[28];
    const float* tln2g   = (const float*)d_in[29];
    const float* tln2b   = (const float*)d_in[30];
    const float* W_out   = (const float*)d_in[31];
    float* out = (float*)d_out;

    float *p_, *y_, *e_, *bias_, *qkv_, *a_, *y1_, *h_, *f_, *mem_;
    uint32_t *wh_, *wl_;
    cudaGetSymbolAddress((void**)&p_,    d_p);
    cudaGetSymbolAddress((void**)&y_,    d_y);
    cudaGetSymbolAddress((void**)&e_,    d_e);
    cudaGetSymbolAddress((void**)&bias_, d_bias);
    cudaGetSymbolAddress((void**)&qkv_,  d_qkv);
    cudaGetSymbolAddress((void**)&a_,    d_a);
    cudaGetSymbolAddress((void**)&y1_,   d_y1);
    cudaGetSymbolAddress((void**)&h_,    d_h);
    cudaGetSymbolAddress((void**)&f_,    d_f);
    cudaGetSymbolAddress((void**)&mem_,  d_mem);
    cudaGetSymbolAddress((void**)&wh_,   d_wh);
    cudaGetSymbolAddress((void**)&wl_,   d_wl);

    // weight split offsets (u32 units)
    const int oWpose = 0;
    const int oWemb  = 2048;
    const int oGqkv  = 10240;
    const int oGWo   = 59392;
    const int oGW1   = 75776;
    const int oGW2   = 108544;
    const int oDeW   = 141312;
    const int oTqkv  = 157696;
    const int oTWo   = 206848;
    const int oTW1   = 223232;
    const int oTW2   = 256000;
    const int oWout  = 288768;

    PrepList pl;
    int wi = 0;
    auto addw = [&](const float* s, int off, int n) {
        pl.src[wi] = s; pl.off[wi] = off; pl.n[wi] = n; wi++;
    };
    addw(W_pose, oWpose, 2048);
    addw(W_emb,               oWemb,        4096);
    addw(W_emb + 8192,        oWemb + 4096, 4096);
    addw(gWqkv,               oGqkv,          24576);
    addw(gWqkv + 49152,       oGqkv + 24576,  24576);
    addw(gWo,                 oGWo,           8192);
    addw(gWo + 16384,         oGWo + 8192,    8192);
    addw(gW1,                 oGW1,           16384);
    addw(gW1 + 32768,         oGW1 + 16384,   16384);
    addw(gW2,                 oGW2,           16384);
    addw(gW2 + 32768,         oGW2 + 16384,   16384);
    addw(deW,                 oDeW,           8192);
    addw(deW + 16384,         oDeW + 8192,    8192);
    addw(tWqkv,               oTqkv,          24576);
    addw(tWqkv + 49152,       oTqkv + 24576,  24576);
    addw(tWo,                 oTWo,           8192);
    addw(tWo + 16384,         oTWo + 8192,    8192);
    addw(tW1,                 oTW1,           16384);
    addw(tW1 + 32768,         oTW1 + 16384,   16384);
    addw(tW2,                 oTW2,           16384);
    addw(tW2 + 32768,         oTW2 + 16384,   16384);
    addw(W_out, oWout, 4096);

    split_weights_kernel<<<dim3(48, NW), 256>>>(pl);
    build_p_kernel<<<(NTOK * CC + 255) / 256, 256>>>(pose);
    build_pe_kernel<<<TT, DD>>>();

    GEMM(p_, wh_ + oWpose, wl_ + oWpose, nullptr, y_, NTOK, 128, 32, 0);

    for (int it = 0; it < 2; it++) {
        GEMM(p_, wh_ + oWemb + it * 4096, wl_ + oWemb + it * 4096, nullptr, e_,
             NTOK, 256, 32, 0);
        bias_kernel<<<NBT, 256>>>(e_, W_bias + (size_t)it * HH * HDm, prelu_a, it, bias_);

        // ---- graph encoder block ----
        GEMM(y_, wh_ + oGqkv + it * 24576, wl_ + oGqkv + it * 24576,
             gbqkv + (size_t)it * 3 * DD, qkv_, NTOK, 384, 128, 0);
        graph_attn_kernel<<<NBT, 256>>>(qkv_, bias_, a_);
        GEMM(a_, wh_ + oGWo + it * 8192, wl_ + oGWo + it * 8192,
             gbo + (size_t)it * DD, f_, NTOK, 128, 128, 0);
        ln_kernel<<<(NTOK + 7) / 8, 256>>>(f_, y_, gln1g + it * DD, gln1b + it * DD, y1_, nullptr);
        GEMM(y1_, wh_ + oGW1 + it * 16384, wl_ + oGW1 + it * 16384,
             gb1 + (size_t)it * HDm, h_, NTOK, 256, 128, 1);
        GEMM(h_, wh_ + oGW2 + it * 16384, wl_ + oGW2 + it * 16384,
             gb2 + (size_t)it * DD, f_, NTOK, 128, 256, 0);
        ln_kernel<<<(NTOK + 7) / 8, 256>>>(f_, y1_, gln2g + it * DD, gln2b + it * DD, a_, nullptr);
        GEMM(a_, wh_ + oDeW + it * 8192, wl_ + oDeW + it * 8192,
             deb + (size_t)it * DD, y_, NTOK, 128, 128, 3, mem_);

        // ---- temporal encoder block ----
        GEMM(y_, wh_ + oTqkv + it * 24576, wl_ + oTqkv + it * 24576,
             tbqkv + (size_t)it * 3 * DD, qkv_, NTOK, 384, 128, 0);
        {
            dim3 grid(BB * VV, HH);
            temporal_attn_kernel<<<grid, 128>>>(qkv_, a_);
        }
        GEMM(a_, wh_ + oTWo + it * 8192, wl_ + oTWo + it * 8192,
             tbo + (size_t)it * DD, f_, NTOK, 128, 128, 0);
        ln_kernel<<<(NTOK + 7) / 8, 256>>>(f_, y_, tln1g + it * DD, tln1b + it * DD, y1_, nullptr);
        GEMM(y1_, wh_ + oTW1 + it * 16384, wl_ + oTW1 + it * 16384,
             tb1 + (size_t)it * HDm, h_, NTOK, 256, 128, 1);
        GEMM(h_, wh_ + oTW2 + it * 16384, wl_ + oTW2 + it * 16384,
             tb2 + (size_t)it * DD, f_, NTOK, 128, 256, 0);
        ln_kernel<<<(NTOK + 7) / 8, 256>>>(f_, y1_, tln2g + it * DD, tln2b + it * DD, y_, mem_);
    }

    // out = leakyrelu(y @ W_out^T)
    GEMM(y_, wh_ + oWout, wl_ + oWout, nullptr, out, NTOK, 64, 128, 2);
}

// round 13
// speedup vs baseline: 1.7484x; 1.0060x over previous
#include <cuda_runtime.h>
#include <cuda_bf16.h>
#include <math.h>
#include <stdint.h>

// Problem constants
#define BB   16
#define CC   32
#define TT   62
#define VV   19
#define DD   128
#define HH   8
#define HDm  256
#define NBT  (BB*TT)      // 992
#define NTOK (NBT*VV)     // 18848
#define NPAIR (VV*VV)     // 361

// ---------------- scratch buffers ----------------
__device__ float d_p   [NTOK*CC];
__device__ float d_y   [NTOK*DD];
__device__ float d_e   [NTOK*HDm];
__device__ float d_bias[NBT*NPAIR*HH];
__device__ float d_qkv [NTOK*384];
__device__ float d_a   [NTOK*DD];
__device__ float d_y1  [NTOK*DD];
__device__ float d_h   [NTOK*HDm];
__device__ float d_f   [NTOK*DD];
__device__ float d_mem [NTOK*DD];
__device__ float d_pe  [TT*DD];
// pre-split weights (bf16 hi/lo packed as u32 = 2 bf16)
#define WTOT 292864
__device__ uint32_t d_wh[WTOT];
__device__ uint32_t d_wl[WTOT];

// ---------------- helpers ----------------
__device__ __forceinline__ void cvt_split2(float x, float y, uint32_t& hi, uint32_t& lo) {
    __nv_bfloat16 xh = __float2bfloat16(x);
    __nv_bfloat16 yh = __float2bfloat16(y);
    __nv_bfloat16 xl = __float2bfloat16(x - __bfloat162float(xh));
    __nv_bfloat16 yl = __float2bfloat16(y - __bfloat162float(yh));
    hi = ((uint32_t)__bfloat16_as_ushort(yh) << 16) | (uint32_t)__bfloat16_as_ushort(xh);
    lo = ((uint32_t)__bfloat16_as_ushort(yl) << 16) | (uint32_t)__bfloat16_as_ushort(xl);
}

__device__ __forceinline__ void mma16816(float (&c)[4], const uint32_t (&a)[4],
                                         uint32_t b0, uint32_t b1) {
    asm volatile(
        "mma.sync.aligned.m16n8k16.row.col.f32.bf16.bf16.f32 "
        "{%0,%1,%2,%3}, {%4,%5,%6,%7}, {%8,%9}, {%0,%1,%2,%3};"
        : "+f"(c[0]), "+f"(c[1]), "+f"(c[2]), "+f"(c[3])
        : "r"(a[0]), "r"(a[1]), "r"(a[2]), "r"(a[3]), "r"(b0), "r"(b1));
}

__device__ __forceinline__ void ldsm4(uint32_t (&r)[4], uint32_t base, int row, int ks, int chalf) {
    int chunk = 2 * ks + chalf;
    int cp = chunk ^ ((row & 6) >> 1);
    uint32_t addr = base + (uint32_t)(row * 64 + cp * 16);
    asm volatile("ldmatrix.sync.aligned.m8n8.x4.shared.b16 {%0,%1,%2,%3}, [%4];"
        : "=r"(r[0]), "=r"(r[1]), "=r"(r[2]), "=r"(r[3]) : "r"(addr));
}

// ---------------- p builder ----------------
__global__ void build_p_kernel(const float* __restrict__ pose) {
    int idx = blockIdx.x * 256 + threadIdx.x;
    if (idx >= NTOK * CC) return;
    int c  = idx & 31;
    int v  = (idx >> 5) % VV;
    int bt = idx / (CC * VV);
    int b = bt / TT, t = bt % TT;
    d_p[idx] = pose[(((size_t)b * CC + c) * TT + t) * VV + v];
}

// ---------------- positional encoding ----------------
__global__ void build_pe_kernel() {
    int t = blockIdx.x, c = threadIdx.x;
    int i2 = c & ~1;
    float div = expf((float)i2 * (-9.210340371976184f / 128.f));
    float ang = (float)t * div;
    d_pe[t * DD + c] = (c & 1) ? cosf(ang) : sinf(ang);
}

// ---------------- weight pre-split ----------------
#define NW 22
struct PrepList {
    const float* src[NW];
    int off[NW];
    int n[NW];
};
__global__ void split_weights_kernel(PrepList pl) {
    int wi = blockIdx.y;
    const float* s = pl.src[wi];
    int off = pl.off[wi], n = pl.n[wi];
    for (int i = blockIdx.x * blockDim.x + threadIdx.x; i < n; i += gridDim.x * blockDim.x) {
        uint32_t hi, lo;
        cvt_split2(s[2 * i], s[2 * i + 1], hi, lo);
        d_wh[off + i] = hi;
        d_wl[off + i] = lo;
    }
}

// ================= tensor-core GEMM v3 (R11 winner, unchanged) =================
__global__ __launch_bounds__(256, 2)
void gemm_tc3(const float* __restrict__ A, const uint32_t* __restrict__ WH,
              const uint32_t* __restrict__ WL, const float* __restrict__ bias,
              float* __restrict__ C, float* __restrict__ C2,
              int M, int N, int K, int act)
{
    __shared__ __align__(16) uint32_t Ah_s[2][64 * 16];
    __shared__ __align__(16) uint32_t Al_s[2][64 * 16];
    __shared__ __align__(16) uint32_t Bh_s[2][128 * 16];
    __shared__ __align__(16) uint32_t Bl_s[2][128 * 16];

    int tid = threadIdx.x, lane = tid & 31, wid = tid >> 5;
    int m0 = blockIdx.x * 64, n0 = blockIdx.y * 128;
    int wm = (wid & 1) * 32, wn = (wid >> 1) * 32;
    int gr = lane >> 2, gc = lane & 3;
    int rl = lane & 15, chalf = lane >> 4;

    int arow = tid >> 2, aq = tid & 3;
    int acp = aq ^ ((arow & 6) >> 1);
    uint32_t aoff = (uint32_t)(arow * 16 + acp * 4);
    int brow = tid >> 1, bq = tid & 1;
    int bsw = (brow & 6) >> 1;
    uint32_t boff0 = (uint32_t)(brow * 16 + ((2 * bq)     ^ bsw) * 4);
    uint32_t boff1 = (uint32_t)(brow * 16 + ((2 * bq + 1) ^ bsw) * 4);

    float af[8];
    uint4 whr0, whr1, wlr0, wlr1;
    const uint4 z4 = make_uint4(0u, 0u, 0u, 0u);
    int KH = K >> 1;
    bool okA = (m0 + arow) < M;
    bool okB = (n0 + brow) < N;
    const float* aptr = A + (size_t)(m0 + arow) * K + aq * 8;
    const uint4* bhp = (const uint4*)(WH + (size_t)(n0 + brow) * KH + bq * 8);
    const uint4* blp = (const uint4*)(WL + (size_t)(n0 + brow) * KH + bq * 8);

    float acc[2][4][4];
    #pragma unroll
    for (int mt = 0; mt < 2; mt++)
        #pragma unroll
        for (int nt = 0; nt < 4; nt++)
            #pragma unroll
            for (int e = 0; e < 4; e++) acc[mt][nt][e] = 0.f;

    {
        #pragma unroll
        for (int q = 0; q < 8; q++) af[q] = 0.f;
        if (okA) {
            float4 v0 = *(const float4*)(aptr);
            float4 v1 = *(const float4*)(aptr + 4);
            af[0]=v0.x; af[1]=v0.y; af[2]=v0.z; af[3]=v0.w;
            af[4]=v1.x; af[5]=v1.y; af[6]=v1.z; af[7]=v1.w;
        }
        whr0 = okB ? bhp[0] : z4;  whr1 = okB ? bhp[1] : z4;
        wlr0 = okB ? blp[0] : z4;  wlr1 = okB ? blp[1] : z4;
        uint32_t h[4], l[4];
        #pragma unroll
        for (int q = 0; q < 4; q++) cvt_split2(af[2*q], af[2*q+1], h[q], l[q]);
        *(uint4*)&Ah_s[0][aoff] = make_uint4(h[0], h[1], h[2], h[3]);
        *(uint4*)&Al_s[0][aoff] = make_uint4(l[0], l[1], l[2], l[3]);
        *(uint4*)&Bh_s[0][boff0] = whr0;  *(uint4*)&Bh_s[0][boff1] = whr1;
        *(uint4*)&Bl_s[0][boff0] = wlr0;  *(uint4*)&Bl_s[0][boff1] = wlr1;
    }
    __syncthreads();

    int nk = K / 32;
    for (int kt = 0; kt < nk; kt++) {
        int cur = kt & 1;
        if (kt + 1 < nk) {
            int k0 = (kt + 1) * 32;
            if (okA) {
                const float* as = aptr + k0;
                float4 v0 = *(const float4*)(as);
                float4 v1 = *(const float4*)(as + 4);
                af[0]=v0.x; af[1]=v0.y; af[2]=v0.z; af[3]=v0.w;
                af[4]=v1.x; af[5]=v1.y; af[6]=v1.z; af[7]=v1.w;
            }
            const uint4* ph = bhp + (k0 >> 3);
            const uint4* pl = blp + (k0 >> 3);
            whr0 = okB ? ph[0] : z4;  whr1 = okB ? ph[1] : z4;
            wlr0 = okB ? pl[0] : z4;  wlr1 = okB ? pl[1] : z4;
        }

        uint32_t baseAh = (uint32_t)__cvta_generic_to_shared(&Ah_s[cur][0]);
        uint32_t baseAl = (uint32_t)__cvta_generic_to_shared(&Al_s[cur][0]);
        uint32_t baseBh = (uint32_t)__cvta_generic_to_shared(&Bh_s[cur][0]);
        uint32_t baseBl = (uint32_t)__cvta_generic_to_shared(&Bl_s[cur][0]);

        #pragma unroll
        for (int ks = 0; ks < 2; ks++) {
            uint32_t aH[2][4], aL[2][4], bH[2][4], bL[2][4];
            #pragma unroll
            for (int mt = 0; mt < 2; mt++) ldsm4(aH[mt], baseAh, wm + mt * 16 + rl, ks, chalf);
            #pragma unroll
            for (int p = 0; p < 2; p++)    ldsm4(bH[p],  baseBh, wn + p * 16 + rl, ks, chalf);
            #pragma unroll
            for (int mt = 0; mt < 2; mt++)
                #pragma unroll
                for (int nti = 0; nti < 4; nti++) {
                    int ntp = nti >> 1, o = nti & 1;
                    mma16816(acc[mt][nti], aH[mt], bH[ntp][o], bH[ntp][o + 2]);
                }
            #pragma unroll
            for (int p = 0; p < 2; p++)    ldsm4(bL[p],  baseBl, wn + p * 16 + rl, ks, chalf);
            #pragma unroll
            for (int mt = 0; mt < 2; mt++)
                #pragma unroll
                for (int nti = 0; nti < 4; nti++) {
                    int ntp = nti >> 1, o = nti & 1;
                    mma16816(acc[mt][nti], aH[mt], bL[ntp][o], bL[ntp][o + 2]);
                }
            #pragma unroll
            for (int mt = 0; mt < 2; mt++) ldsm4(aL[mt], baseAl, wm + mt * 16 + rl, ks, chalf);
            #pragma unroll
            for (int mt = 0; mt < 2; mt++)
                #pragma unroll
                for (int nti = 0; nti < 4; nti++) {
                    int ntp = nti >> 1, o = nti & 1;
                    mma16816(acc[mt][nti], aL[mt], bH[ntp][o], bH[ntp][o + 2]);
                }
        }

        if (kt + 1 < nk) {
            int nb = cur ^ 1;
            uint32_t h[4], l[4];
            #pragma unroll
            for (int q = 0; q < 4; q++) cvt_split2(af[2*q], af[2*q+1], h[q], l[q]);
            *(uint4*)&Ah_s[nb][aoff] = make_uint4(h[0], h[1], h[2], h[3]);
            *(uint4*)&Al_s[nb][aoff] = make_uint4(l[0], l[1], l[2], l[3]);
            *(uint4*)&Bh_s[nb][boff0] = whr0;  *(uint4*)&Bh_s[nb][boff1] = whr1;
            *(uint4*)&Bl_s[nb][boff0] = wlr0;  *(uint4*)&Bl_s[nb][boff1] = wlr1;
            __syncthreads();
        }
    }

    #pragma unroll
    for (int mt = 0; mt < 2; mt++) {
        #pragma unroll
        for (int rr = 0; rr < 2; rr++) {
            int row = m0 + wm + mt * 16 + gr + rr * 8;
            if (row >= M) continue;
            #pragma unroll
            for (int nti = 0; nti < 4; nti++) {
                int col = n0 + wn + nti * 8 + gc * 2;
                if (col >= N) continue;
                float v0 = acc[mt][nti][rr * 2];
                float v1 = acc[mt][nti][rr * 2 + 1];
                if (bias) { v0 += bias[col]; v1 += bias[col + 1]; }
                if (act == 1) { v0 = fmaxf(v0, 0.f); v1 = fmaxf(v1, 0.f); }
                else if (act == 2) {
                    v0 = (v0 >= 0.f) ? v0 : 0.01f * v0;
                    v1 = (v1 >= 0.f) ? v1 : 0.01f * v1;
                }
                else if (act == 3) {
                    v0 += d_pe[(row % TT) * DD + (col & 127)];
                    v1 += d_pe[(row % TT) * DD + ((col + 1) & 127)];
                }
                *(float2*)(C + (size_t)row * N + col) = make_float2(v0, v1);
                if (act == 3)
                    *(float2*)(C2 + (size_t)row * N + col) = make_float2(v0, v1);
            }
        }
    }
}

// ---------------- fused pairwise bias (v2: k-major W_bias, LDS.128) ----------------
__global__ __launch_bounds__(256)
void bias_kernel(const float* __restrict__ E, const float* __restrict__ WB,
                 const float* __restrict__ prelu_a, int iter, float* __restrict__ OUT)
{
    __shared__ float es[VV * HDm];
    __shared__ __align__(16) float wb_t[HDm * HH];   // [k][g]
    int bt = blockIdx.x;
    int tid = threadIdx.x;
    for (int idx = tid; idx < VV * HDm; idx += 256)
        es[idx] = E[((size_t)bt * VV) * HDm + idx];
    for (int idx = tid; idx < HH * HDm; idx += 256) {
        int g = idx >> 8, k = idx & 255;      // WB is [g][k]
        wb_t[k * 8 + g] = WB[idx];
    }
    float aP = prelu_a[iter];
    __syncthreads();

    int warp = tid >> 5, lane = tid & 31;
    for (int pr = warp; pr < NPAIR; pr += 8) {
        int vi = pr / VV, vj = pr % VV;
        float acc[8] = {0,0,0,0,0,0,0,0};
        #pragma unroll
        for (int u = 0; u < 8; u++) {
            int k = u * 32 + lane;
            float hv = es[vj * HDm + k] - es[vi * HDm + k];
            hv = (hv >= 0.f) ? hv : aP * hv;
            float4 w0 = *(const float4*)&wb_t[k * 8];
            float4 w1 = *(const float4*)&wb_t[k * 8 + 4];
            acc[0] += hv * w0.x; acc[1] += hv * w0.y;
            acc[2] += hv * w0.z; acc[3] += hv * w0.w;
            acc[4] += hv * w1.x; acc[5] += hv * w1.y;
            acc[6] += hv * w1.z; acc[7] += hv * w1.w;
        }
        #pragma unroll
        for (int g = 0; g < 8; g++)
            #pragma unroll
            for (int o = 16; o; o >>= 1)
                acc[g] += __shfl_xor_sync(0xffffffffu, acc[g], o);
        if (lane == 0) {
            float* o = OUT + (((size_t)bt * VV + vi) * VV + vj) * HH;
            #pragma unroll
            for (int g = 0; g < 8; g++) o[g] = acc[g] * 0.3535533906f;
        }
    }
}

// ---------------- graph attention (512 threads; warp = (head, i-parity)) ----------------
__global__ __launch_bounds__(512)
void graph_attn_kernel(const float* __restrict__ QKV, const float* __restrict__ BIAS,
                       float* __restrict__ OUT)
{
    __shared__ float qs[VV * DD];
    __shared__ float ks[DD * VV];
    __shared__ float vs[DD * VV];
    int bt = blockIdx.x;
    int tid = threadIdx.x;
    for (int idx = tid; idx < VV * DD; idx += 512) {
        int n = idx >> 7, c = idx & 127;
        const float* row = QKV + (size_t)(bt * VV + n) * 384;
        qs[idx] = row[c];
        ks[c * VV + n] = row[128 + c];
        vs[c * VV + n] = row[256 + c];
    }
    __syncthreads();
    int wid = tid >> 5, lane = tid & 31;
    int h = wid & 7, ih = wid >> 3;
    for (int i = ih; i < VV; i += 2) {
        float sc = -1e30f;
        if (lane < VV) {
            float acc = 0.f;
            #pragma unroll
            for (int c = 0; c < 16; c++)
                acc += qs[i * DD + h * 16 + c] * ks[(h * 16 + c) * VV + lane];
            sc = acc * 0.25f + BIAS[(((size_t)bt * VV + i) * VV + lane) * HH + h];
        }
        float mx = sc;
        #pragma unroll
        for (int o = 16; o; o >>= 1) mx = fmaxf(mx, __shfl_xor_sync(0xffffffffu, mx, o));
        float ev = (lane < VV) ? __expf(sc - mx) : 0.f;
        float sum = ev;
        #pragma unroll
        for (int o = 16; o; o >>= 1) sum += __shfl_xor_sync(0xffffffffu, sum, o);
        float aj = ev / sum;
        float o_acc = 0.f;
        int cc = lane & 15;
        #pragma unroll
        for (int j = 0; j < VV; j++) {
            float aw = __shfl_sync(0xffffffffu, aj, j);
            o_acc += aw * vs[(h * 16 + cc) * VV + j];
        }
        if (lane < 16) OUT[(size_t)(bt * VV + i) * DD + h * 16 + lane] = o_acc;
    }
}

// ---------------- temporal attention (256 threads; 8 warps stride rows) ----------------
__global__ __launch_bounds__(256)
void temporal_attn_kernel(const float* __restrict__ QKV, float* __restrict__ OUT)
{
    __shared__ float ks[16 * 65];
    __shared__ float vs[16 * 65];
    int bn = blockIdx.x, h = blockIdx.y;
    int tid = threadIdx.x;
    for (int idx = tid; idx < 16 * 64; idx += 256) {
        int c = idx >> 6, n = idx & 63;
        float kv = 0.f, vv = 0.f;
        if (n < TT) {
            const float* row = QKV + (size_t)(bn * TT + n) * 384 + h * 16 + c;
            kv = row[128];
            vv = row[256];
        }
        ks[c * 65 + n] = kv;
        vs[c * 65 + n] = vv;
    }
    __syncthreads();
    int warp = tid >> 5, lane = tid & 31;
    for (int i = warp; i < TT; i += 8) {
        float q = (lane < 16) ? QKV[(size_t)(bn * TT + i) * 384 + h * 16 + lane] : 0.f;
        float s0 = 0.f, s1 = 0.f;
        #pragma unroll
        for (int c = 0; c < 16; c++) {
            float qc = __shfl_sync(0xffffffffu, q, c);
            s0 += qc * ks[c * 65 + lane];
            s1 += qc * ks[c * 65 + lane + 32];
        }
        s0 *= 0.25f; s1 *= 0.25f;
        bool v1 = (lane + 32) < TT;
        float mx = fmaxf(s0, v1 ? s1 : -1e30f);
        #pragma unroll
        for (int o = 16; o; o >>= 1) mx = fmaxf(mx, __shfl_xor_sync(0xffffffffu, mx, o));
        float e0 = __expf(s0 - mx);
        float e1 = v1 ? __expf(s1 - mx) : 0.f;
        float sum = e0 + e1;
        #pragma unroll
        for (int o = 16; o; o >>= 1) sum += __shfl_xor_sync(0xffffffffu, sum, o);
        float inv = 1.f / sum;
        e0 *= inv; e1 *= inv;
        float o_acc = 0.f;
        int cc = lane & 15;
        #pragma unroll
        for (int j = 0; j < 32; j++) {
            float aw = __shfl_sync(0xffffffffu, e0, j);
            o_acc += aw * vs[cc * 65 + j];
        }
        #pragma unroll
        for (int j = 32; j < TT; j++) {
            float aw = __shfl_sync(0xffffffffu, e1, j - 32);
            o_acc += aw * vs[cc * 65 + j];
        }
        if (lane < 16) OUT[(size_t)(bn * TT + i) * DD + h * 16 + lane] = o_acc;
    }
}

// ---------------- LayerNorm (float4): out = LN(X + R) * g + b (+ ADD) ----------------
__global__ __launch_bounds__(256)
void ln_kernel(const float* __restrict__ X, const float* __restrict__ R,
               const float* __restrict__ g, const float* __restrict__ b,
               float* __restrict__ OUT, const float* __restrict__ ADD)
{
    int warp = threadIdx.x >> 5, lane = threadIdx.x & 31;
    int row = blockIdx.x * 8 + warp;
    if (row >= NTOK) return;
    int c4 = lane * 4;
    float4 xv = *(const float4*)(X + (size_t)row * DD + c4);
    float4 rv = *(const float4*)(R + (size_t)row * DD + c4);
    float v[4] = {xv.x + rv.x, xv.y + rv.y, xv.z + rv.z, xv.w + rv.w};
    float s = v[0] + v[1] + v[2] + v[3];
    #pragma unroll
    for (int o = 16; o; o >>= 1) s += __shfl_xor_sync(0xffffffffu, s, o);
    float m = s * (1.f / 128.f);
    float sv = 0.f;
    #pragma unroll
    for (int u = 0; u < 4; u++) { float dlt = v[u] - m; sv += dlt * dlt; }
    #pragma unroll
    for (int o = 16; o; o >>= 1) sv += __shfl_xor_sync(0xffffffffu, sv, o);
    float rinv = rsqrtf(sv * (1.f / 128.f) + 1e-5f);
    float4 gv = *(const float4*)(g + c4);
    float4 bv = *(const float4*)(b + c4);
    float o0 = (v[0] - m) * rinv * gv.x + bv.x;
    float o1 = (v[1] - m) * rinv * gv.y + bv.y;
    float o2 = (v[2] - m) * rinv * gv.z + bv.z;
    float o3 = (v[3] - m) * rinv * gv.w + bv.w;
    if (ADD) {
        float4 av = *(const float4*)(ADD + (size_t)row * DD + c4);
        o0 += av.x; o1 += av.y; o2 += av.z; o3 += av.w;
    }
    *(float4*)(OUT + (size_t)row * DD + c4) = make_float4(o0, o1, o2, o3);
}

// ---------------- host launcher ----------------
static void GEMM(const float* A, const uint32_t* WH, const uint32_t* WL,
                 const float* bias, float* C, int M, int N, int K, int act,
                 float* C2 = nullptr)
{
    dim3 grid((M + 63) / 64, (N + 127) / 128);
    gemm_tc3<<<grid, 256>>>(A, WH, WL, bias, C, C2, M, N, K, act);
}

extern "C" void kernel_launch(void* const* d_in, const int* in_sizes, int n_in,
                              void* d_out, int out_size)
{
    const float* pose    = (const float*)d_in[0];
    const float* W_pose  = (const float*)d_in[1];
    const float* W_emb   = (const float*)d_in[2];
    const float* prelu_a = (const float*)d_in[3];
    const float* W_bias  = (const float*)d_in[4];
    const float* gWqkv   = (const float*)d_in[5];
    const float* gbqkv   = (const float*)d_in[6];
    const float* gWo     = (const float*)d_in[7];
    const float* gbo     = (const float*)d_in[8];
    const float* gln1g   = (const float*)d_in[9];
    const float* gln1b   = (const float*)d_in[10];
    const float* gW1     = (const float*)d_in[11];
    const float* gb1     = (const float*)d_in[12];
    const float* gW2     = (const float*)d_in[13];
    const float* gb2     = (const float*)d_in[14];
    const float* gln2g   = (const float*)d_in[15];
    const float* gln2b   = (const float*)d_in[16];
    const float* deW     = (const float*)d_in[17];
    const float* deb     = (const float*)d_in[18];
    const float* tWqkv   = (const float*)d_in[19];
    const float* tbqkv   = (const float*)d_in[20];
    const float* tWo     = (const float*)d_in[21];
    const float* tbo     = (const float*)d_in[22];
    const float* tln1g   = (const float*)d_in[23];
    const float* tln1b   = (const float*)d_in[24];
    const float* tW1     = (const float*)d_in[25];
    const float* tb1     = (const float*)d_in[26];
    const float* tW2     = (const float*)d_in[27];
    const float* tb2     = (const float*)d_in[28];
    const float* tln2g   = (const float*)d_in[29];
    const float* tln2b   = (const float*)d_in[30];
    const float* W_out   = (const float*)d_in[31];
    float* out = (float*)d_out;

    float *p_, *y_, *e_, *bias_, *qkv_, *a_, *y1_, *h_, *f_, *mem_;
    uint32_t *wh_, *wl_;
    cudaGetSymbolAddress((void**)&p_,    d_p);
    cudaGetSymbolAddress((void**)&y_,    d_y);
    cudaGetSymbolAddress((void**)&e_,    d_e);
    cudaGetSymbolAddress((void**)&bias_, d_bias);
    cudaGetSymbolAddress((void**)&qkv_,  d_qkv);
    cudaGetSymbolAddress((void**)&a_,    d_a);
    cudaGetSymbolAddress((void**)&y1_,   d_y1);
    cudaGetSymbolAddress((void**)&h_,    d_h);
    cudaGetSymbolAddress((void**)&f_,    d_f);
    cudaGetSymbolAddress((void**)&mem_,  d_mem);
    cudaGetSymbolAddress((void**)&wh_,   d_wh);
    cudaGetSymbolAddress((void**)&wl_,   d_wl);

    // weight split offsets (u32 units)
    const int oWpose = 0;
    const int oWemb  = 2048;
    const int oGqkv  = 10240;
    const int oGWo   = 59392;
    const int oGW1   = 75776;
    const int oGW2   = 108544;
    const int oDeW   = 141312;
    const int oTqkv  = 157696;
    const int oTWo   = 206848;
    const int oTW1   = 223232;
    const int oTW2   = 256000;
    const int oWout  = 288768;

    PrepList pl;
    int wi = 0;
    auto addw = [&](const float* s, int off, int n) {
        pl.src[wi] = s; pl.off[wi] = off; pl.n[wi] = n; wi++;
    };
    addw(W_pose, oWpose, 2048);
    addw(W_emb,               oWemb,        4096);
    addw(W_emb + 8192,        oWemb + 4096, 4096);
    addw(gWqkv,               oGqkv,          24576);
    addw(gWqkv + 49152,       oGqkv + 24576,  24576);
    addw(gWo,                 oGWo,           8192);
    addw(gWo + 16384,         oGWo + 8192,    8192);
    addw(gW1,                 oGW1,           16384);
    addw(gW1 + 32768,         oGW1 + 16384,   16384);
    addw(gW2,                 oGW2,           16384);
    addw(gW2 + 32768,         oGW2 + 16384,   16384);
    addw(deW,                 oDeW,           8192);
    addw(deW + 16384,         oDeW + 8192,    8192);
    addw(tWqkv,               oTqkv,          24576);
    addw(tWqkv + 49152,       oTqkv + 24576,  24576);
    addw(tWo,                 oTWo,           8192);
    addw(tWo + 16384,         oTWo + 8192,    8192);
    addw(tW1,                 oTW1,           16384);
    addw(tW1 + 32768,         oTW1 + 16384,   16384);
    addw(tW2,                 oTW2,           16384);
    addw(tW2 + 32768,         oTW2 + 16384,   16384);
    addw(W_out, oWout, 4096);

    split_weights_kernel<<<dim3(48, NW), 256>>>(pl);
    build_p_kernel<<<(NTOK * CC + 255) / 256, 256>>>(pose);
    build_pe_kernel<<<TT, DD>>>();

    GEMM(p_, wh_ + oWpose, wl_ + oWpose, nullptr, y_, NTOK, 128, 32, 0);

    for (int it = 0; it < 2; it++) {
        GEMM(p_, wh_ + oWemb + it * 4096, wl_ + oWemb + it * 4096, nullptr, e_,
             NTOK, 256, 32, 0);
        bias_kernel<<<NBT, 256>>>(e_, W_bias + (size_t)it * HH * HDm, prelu_a, it, bias_);

        // ---- graph encoder block ----
        GEMM(y_, wh_ + oGqkv + it * 24576, wl_ + oGqkv + it * 24576,
             gbqkv + (size_t)it * 3 * DD, qkv_, NTOK, 384, 128, 0);
        graph_attn_kernel<<<NBT, 512>>>(qkv_, bias_, a_);
        GEMM(a_, wh_ + oGWo + it * 8192, wl_ + oGWo + it * 8192,
             gbo + (size_t)it * DD, f_, NTOK, 128, 128, 0);
        ln_kernel<<<(NTOK + 7) / 8, 256>>>(f_, y_, gln1g + it * DD, gln1b + it * DD, y1_, nullptr);
        GEMM(y1_, wh_ + oGW1 + it * 16384, wl_ + oGW1 + it * 16384,
             gb1 + (size_t)it * HDm, h_, NTOK, 256, 128, 1);
        GEMM(h_, wh_ + oGW2 + it * 16384, wl_ + oGW2 + it * 16384,
             gb2 + (size_t)it * DD, f_, NTOK, 128, 256, 0);
        ln_kernel<<<(NTOK + 7) / 8, 256>>>(f_, y1_, gln2g + it * DD, gln2b + it * DD, a_, nullptr);
        GEMM(a_, wh_ + oDeW + it * 8192, wl_ + oDeW + it * 8192,
             deb + (size_t)it * DD, y_, NTOK, 128, 128, 3, mem_);

        // ---- temporal encoder block ----
        GEMM(y_, wh_ + oTqkv + it * 24576, wl_ + oTqkv + it * 24576,
             tbqkv + (size_t)it * 3 * DD, qkv_, NTOK, 384, 128, 0);
        {
            dim3 grid(BB * VV, HH);
            temporal_attn_kernel<<<grid, 256>>>(qkv_, a_);
        }
        GEMM(a_, wh_ + oTWo + it * 8192, wl_ + oTWo + it * 8192,
             tbo + (size_t)it * DD, f_, NTOK, 128, 128, 0);
        ln_kernel<<<(NTOK + 7) / 8, 256>>>(f_, y_, tln1g + it * DD, tln1b + it * DD, y1_, nullptr);
        GEMM(y1_, wh_ + oTW1 + it * 16384, wl_ + oTW1 + it * 16384,
             tb1 + (size_t)it * HDm, h_, NTOK, 256, 128, 1);
        GEMM(h_, wh_ + oTW2 + it * 16384, wl_ + oTW2 + it * 16384,
             tb2 + (size_t)it * DD, f_, NTOK, 128, 256, 0);
        ln_kernel<<<(NTOK + 7) / 8, 256>>>(f_, y1_, tln2g + it * DD, tln2b + it * DD, y_, mem_);
    }

    // out = leakyrelu(y @ W_out^T)
    GEMM(y_, wh_ + oWout, wl_ + oWout, nullptr, out, NTOK, 64, 128, 2);
}